// round 14
// baseline (speedup 1.0000x reference)
#include <cuda_runtime.h>
#include <cuda_fp16.h>
#include <math.h>
#include <stdint.h>

#define BATCH   8
#define L       1024
#define D       1024
#define H       16
#define DQ      64
#define DFF     4096
#define NLAYERS 6
#define MROWS   (BATCH*L)   // 8192

// ================= scratch (static device globals) ==========================
__device__ float        g_pe[L*D];
__device__ double       g_invdiv[D/2];
__device__ unsigned int g_mbits[BATCH*L*(L/32)];
__device__ float        g_h[MROWS*D];
__device__ float        g_t[MROWS*D];
__device__ __half       g_h16[(size_t)MROWS*D];
__device__ __half       g_qkv16[(size_t)MROWS*3072];
__device__ __half       g_ctx16[(size_t)MROWS*D];
__device__ __half       g_ff16[(size_t)MROWS*DFF];
// packed transposed fp16 weights
__device__ __half       g_wqkv16[(size_t)NLAYERS*3072*1024];
__device__ __half       g_wo16[(size_t)NLAYERS*D*D];
__device__ __half       g_w116[(size_t)NLAYERS*DFF*D];
__device__ __half       g_w216[(size_t)NLAYERS*D*DFF];
// layer-6 small-path buffers (8 last-token rows)
__device__ float        g_trow[8*D];
__device__ float        g_hrow[8*D];
__device__ __half       g_hrow16[8*D];
__device__ __half       g_frow16[8*DFF];
__device__ float        g_hfin[8*D];

// ================= ptx helpers ==============================================
__device__ __forceinline__ uint32_t smem_u32(const void* p) {
    uint32_t a;
    asm("{ .reg .u64 t; cvta.to.shared.u64 t, %1; cvt.u32.u64 %0, t; }" : "=r"(a) : "l"(p));
    return a;
}
__device__ __forceinline__ void cp16(uint32_t dst, const void* src) {
    asm volatile("cp.async.cg.shared.global [%0], [%1], 16;" :: "r"(dst), "l"(src) : "memory");
}
#define CP_COMMIT() asm volatile("cp.async.commit_group;" ::: "memory")
#define CP_WAIT1()  asm volatile("cp.async.wait_group 1;" ::: "memory")
#define CP_WAIT0()  asm volatile("cp.async.wait_group 0;" ::: "memory")

#define LDSM_X4(R, a) \
    asm volatile("ldmatrix.sync.aligned.m8n8.x4.shared.b16 {%0,%1,%2,%3}, [%4];" \
        : "=r"((R)[0]), "=r"((R)[1]), "=r"((R)[2]), "=r"((R)[3]) : "r"(a))
#define LDSM_X2(R, a) \
    asm volatile("ldmatrix.sync.aligned.m8n8.x2.shared.b16 {%0,%1}, [%2];" \
        : "=r"((R)[0]), "=r"((R)[1]) : "r"(a))
#define LDSM_X2T(R, a) \
    asm volatile("ldmatrix.sync.aligned.m8n8.x2.trans.shared.b16 {%0,%1}, [%2];" \
        : "=r"((R)[0]), "=r"((R)[1]) : "r"(a))
#define MMA16816(C, A, B0, B1) \
    asm volatile("mma.sync.aligned.m16n8k16.row.col.f32.f16.f16.f32 " \
        "{%0,%1,%2,%3}, {%4,%5,%6,%7}, {%8,%9}, {%0,%1,%2,%3};" \
        : "+f"((C)[0]), "+f"((C)[1]), "+f"((C)[2]), "+f"((C)[3]) \
        : "r"((A)[0]), "r"((A)[1]), "r"((A)[2]), "r"((A)[3]), "r"(B0), "r"(B1))

// fast 2^y for y <= 0 (FMA-pipe only, no MUFU)
__device__ __forceinline__ float fexp2(float y) {
    y = fmaxf(y, -126.0f);
    float t = y + 12582912.0f;
    int   i = __float_as_int(t);
    float f = y - (t - 12582912.0f);
    float p = 0.00133335581f;
    p = fmaf(p, f, 0.00961812911f);
    p = fmaf(p, f, 0.0555041087f);
    p = fmaf(p, f, 0.240226507f);
    p = fmaf(p, f, 0.693147180f);
    p = fmaf(p, f, 1.0f);
    float sc = __int_as_float((i + (127 - 1262485504)) << 23);
    return sc * p;
}

// ================= small prep kernels =======================================
__global__ void invdiv_kernel() {
    int i = threadIdx.x;
    if (i < D/2) g_invdiv[i] = pow(10000.0, -(2.0*i)/(double)D);
}
__global__ void pe_kernel() {
    int idx = blockIdx.x*256 + threadIdx.x;
    int l = idx >> 9, i = idx & 511;
    const double TWO_PI = 6.283185307179586476925286766559;
    const double INV2PI = 0.15915494309189533576888376337251;
    double ang = (double)(l+1) * g_invdiv[i];
    double r = ang - floor(ang*INV2PI)*TWO_PI;
    float fr = (float)r;
    g_pe[l*D + 2*i]     = sinf(fr);
    g_pe[l*D + 2*i + 1] = cosf(fr);
}
__global__ void mbits_kernel(const int* __restrict__ mask) {
    int idx = blockIdx.x*256 + threadIdx.x;
    const int* p = mask + (size_t)idx * 32;
    unsigned int bits = 0u;
#pragma unroll
    for (int i = 0; i < 32; i++) if (p[i] == 0) bits |= (1u << i);
    g_mbits[idx] = bits;
}
__global__ void embed_kernel(const int* __restrict__ x, const float* __restrict__ emb) {
    int row = blockIdx.x;
    int tid = threadIdx.x;
    int token = x[row];
    int l = row & (L-1);
    const float4* e4 = (const float4*)(emb + (size_t)token*D);
    const float4* p4 = (const float4*)(g_pe + (size_t)l*D);
    float4* h4 = (float4*)(g_h + (size_t)row*D);
    float4 e = e4[tid], p = p4[tid];
    float4 o;
    o.x = e.x*32.0f + p.x; o.y = e.y*32.0f + p.y;
    o.z = e.z*32.0f + p.z; o.w = e.w*32.0f + p.w;
    h4[tid] = o;
    __half* h16 = g_h16 + (size_t)row*D + tid*4;
    h16[0] = __float2half(o.x); h16[1] = __float2half(o.y);
    h16[2] = __float2half(o.z); h16[3] = __float2half(o.w);
}

// transpose + fp32->fp16: generic [K][N] -> [N][K]
__global__ void wtr_kernel(const float* __restrict__ in, __half* __restrict__ out, int K, int N) {
    __shared__ float tile[32][33];
    size_t bs = (size_t)blockIdx.z * K * N;
    int bx = blockIdx.x*32, by = blockIdx.y*32;
    int tx = threadIdx.x, ty = threadIdx.y;
#pragma unroll
    for (int i = 0; i < 32; i += 8)
        tile[ty+i][tx] = in[bs + (size_t)(by+ty+i)*N + bx+tx];
    __syncthreads();
#pragma unroll
    for (int i = 0; i < 32; i += 8)
        out[bs + (size_t)(bx+ty+i)*K + by+tx] = __float2half(tile[tx][ty+i]);
}

// QKV pack: in [layer*16+h][1024][64] -> out [layer][3072 rows][1024]
__global__ void wtr_qkv(const float* __restrict__ in, __half* __restrict__ out, int which) {
    __shared__ float tile[32][33];
    int z = blockIdx.z;
    const float* inp = in + (size_t)z*1024*64;
    __half* outp = out + (size_t)(z >> 4)*3072*1024 + (size_t)which*1024*1024
                       + (size_t)(z & 15)*64*1024;
    int bx = blockIdx.x*32, by = blockIdx.y*32;
    int tx = threadIdx.x, ty = threadIdx.y;
#pragma unroll
    for (int i = 0; i < 32; i += 8)
        tile[ty+i][tx] = inp[(size_t)(by+ty+i)*64 + bx+tx];
    __syncthreads();
#pragma unroll
    for (int i = 0; i < 32; i += 8)
        outp[(size_t)(bx+ty+i)*1024 + by+tx] = __float2half(tile[tx][ty+i]);
}

// ================= HMMA fp16 GEMM: persistent CTAs, 128x128, GBK=64 =========
#define GBM 128
#define GBN 128
#define GBK 64
#define GROWB 144               // 64 halfs (128B) + 16B pad
#define STG  (2*128*GROWB)      // 36864
#define GEMM_SMEM (3*STG)       // 110592
#define NPERS 296               // 148 SMs x 2 CTAs

__device__ __forceinline__ void stage_tile(const __half* A, const __half* B, int K,
                                           int m0, int n0, uint32_t sbase, int kc, int s, int tid) {
    uint32_t base = sbase + s*STG;
    int k0 = kc*GBK;
#pragma unroll
    for (int i = 0; i < 4; i++) {          // A: 128 rows x 8 chunks of 16B
        int e = tid + i*256;
        int r = e >> 3, c = e & 7;
        cp16(base + r*GROWB + c*16, A + (size_t)(m0 + r)*K + k0 + c*8);
    }
    uint32_t bb = base + 128*GROWB;
#pragma unroll
    for (int i = 0; i < 4; i++) {          // B: 128 rows x 8 chunks of 16B
        int e = tid + i*256;
        int r = e >> 3, c = e & 7;
        cp16(bb + r*GROWB + c*16, B + (size_t)(n0 + r)*K + k0 + c*8);
    }
}

template<bool BIAS, bool RELU, int OUT>   // OUT: 0=fp32, 1=fp16
__global__ __launch_bounds__(256, 2)
void gemm_mma(const __half* __restrict__ A, const __half* __restrict__ B,
              const float* __restrict__ bias, void* __restrict__ Cv, int K, int ldc,
              int tilesX, int nTiles, int qskip) {
    extern __shared__ char smem[];
    uint32_t sb = smem_u32(smem);
    int tid = threadIdx.x, lane = tid & 31, wid = tid >> 5;
    int warpM = wid & 1, warpN = wid >> 1;       // 2 x 4 warps, each 64x32
    int NC = K / GBK;

    // lane offsets
    int aj = lane >> 3, ar = lane & 7;
    int a_moff = (aj & 1)*8 + ar;
    int a_koff = (aj >> 1)*8;
    int b4_roff = ((lane >> 4) & 1)*8 + ar;
    int b4_koff = ((lane >> 3) & 1)*8;
    int rrow = lane >> 2, cpair = (lane & 3)*2;

    for (int t = blockIdx.x; t < nTiles; t += gridDim.x) {
        int my = t / tilesX, mx = t - my*tilesX;
        int m0 = my * GBM, n0 = mx * GBN;
        // layer-6 shortcut: Q columns only needed for last m-tile of each batch
        if (qskip && n0 < 1024 && ((my & 7) != 7)) continue;

        __syncthreads();   // protect smem stage reuse across tiles

        float acc[4][4][4] = {};

        stage_tile(A, B, K, m0, n0, sb, 0, 0, tid); CP_COMMIT();
        stage_tile(A, B, K, m0, n0, sb, 1, 1, tid); CP_COMMIT();

        for (int kc = 0; kc < NC; kc++) {
            CP_WAIT1();
            __syncthreads();
            int nk = kc + 2;
            if (nk < NC) stage_tile(A, B, K, m0, n0, sb, nk, nk % 3, tid);
            CP_COMMIT();

            uint32_t aBase = sb + (kc % 3)*STG;
            uint32_t bBase = aBase + 128*GROWB;
#pragma unroll
            for (int ks = 0; ks < GBK; ks += 16) {
                uint32_t a[4][4], b[2][4];
#pragma unroll
                for (int mf = 0; mf < 4; mf++) {
                    int mrow = warpM*64 + mf*16 + a_moff;
                    LDSM_X4(a[mf], aBase + mrow*GROWB + (ks + a_koff)*2);
                }
#pragma unroll
                for (int np = 0; np < 2; np++) {
                    int nrow = warpN*32 + np*16 + b4_roff;
                    LDSM_X4(b[np], bBase + nrow*GROWB + (ks + b4_koff)*2);
                }
#pragma unroll
                for (int mf = 0; mf < 4; mf++) {
#pragma unroll
                    for (int np = 0; np < 2; np++) {
                        MMA16816(acc[mf][2*np],   a[mf], b[np][0], b[np][1]);
                        MMA16816(acc[mf][2*np+1], a[mf], b[np][2], b[np][3]);
                    }
                }
            }
        }
        CP_WAIT0();

#pragma unroll
        for (int mf = 0; mf < 4; mf++) {
#pragma unroll
            for (int nf = 0; nf < 4; nf++) {
                int row = m0 + warpM*64 + mf*16 + rrow;
                int col = n0 + warpN*32 + nf*8 + cpair;
                float b0 = 0.f, b1 = 0.f;
                if (BIAS) { b0 = __ldg(bias + col); b1 = __ldg(bias + col + 1); }
                float v0 = acc[mf][nf][0] + b0, v1 = acc[mf][nf][1] + b1;
                float v2 = acc[mf][nf][2] + b0, v3 = acc[mf][nf][3] + b1;
                if (RELU) {
                    v0 = fmaxf(v0, 0.f); v1 = fmaxf(v1, 0.f);
                    v2 = fmaxf(v2, 0.f); v3 = fmaxf(v3, 0.f);
                }
                if (OUT == 0) {
                    float* C = (float*)Cv;
                    *(float2*)(C + (size_t)row*ldc + col)     = make_float2(v0, v1);
                    *(float2*)(C + (size_t)(row+8)*ldc + col) = make_float2(v2, v3);
                } else {
                    __half* C = (__half*)Cv;
                    *(__half2*)(C + (size_t)row*ldc + col)     = __floats2half2_rn(v0, v1);
                    *(__half2*)(C + (size_t)(row+8)*ldc + col) = __floats2half2_rn(v2, v3);
                }
            }
        }
    }
}

// ================= HMMA flash attention (packed QKV, stride 3072) ===========
#define FH 144                        // bytes per smem row (72 halfs)
#define LDQ 3072
#define SCALE2 0.18033688011112042f   // (1/8) * log2(e)

__global__ __launch_bounds__(128)
void flash_mma(const __half* __restrict__ QKV, __half* __restrict__ C, int l0base) {
    __shared__ __half sQ[64*72];
    __shared__ __half sK[2][64*72];
    __shared__ __half sV[2][64*72];

    int tid = threadIdx.x, lane = tid & 31, w = tid >> 5;
    int z = blockIdx.y, b = z >> 4, hh = z & 15;
    int l0 = l0base + blockIdx.x * 64;

    const __half* Qp  = QKV + ((size_t)(b*L + l0))*LDQ + hh*DQ;
    const __half* Kp0 = QKV + ((size_t)(b*L))*LDQ + 1024 + hh*DQ;
    const __half* Vp0 = QKV + ((size_t)(b*L))*LDQ + 2048 + hh*DQ;

    uint32_t qb = smem_u32(sQ), kb = smem_u32(sK), vb = smem_u32(sV);

#pragma unroll
    for (int i = 0; i < 4; i++) {
        int e = tid + i*128, r = e >> 3, c = e & 7;
        cp16(qb + r*FH + c*16, Qp + (size_t)r*LDQ + c*8);
    }
#pragma unroll
    for (int i = 0; i < 4; i++) {
        int e = tid + i*128, r = e >> 3, c = e & 7;
        cp16(kb + r*FH + c*16, Kp0 + (size_t)r*LDQ + c*8);
        cp16(vb + r*FH + c*16, Vp0 + (size_t)r*LDQ + c*8);
    }
    CP_COMMIT();
#pragma unroll
    for (int i = 0; i < 4; i++) {
        int e = tid + i*128, r = e >> 3, c = e & 7;
        cp16(kb + 9216 + r*FH + c*16, Kp0 + (size_t)(64 + r)*LDQ + c*8);
        cp16(vb + 9216 + r*FH + c*16, Vp0 + (size_t)(64 + r)*LDQ + c*8);
    }
    CP_COMMIT();

    CP_WAIT1();
    __syncthreads();

    uint32_t qf[4][4];
    int qrow = w*16 + (lane & 7) + ((lane >> 3) & 1)*8;
    int qk = (lane >> 4)*8;
#pragma unroll
    for (int ks = 0; ks < 4; ks++)
        LDSM_X4(qf[ks], qb + qrow*FH + (ks*16 + qk)*2);

    int r0loc = w*16 + (lane >> 2);
    int bq = lane & 3;
    const unsigned* mrow0 = g_mbits + ((size_t)(b*L + l0 + r0loc))*32;
    const unsigned* mrow1 = mrow0 + 8*32;

    float m0 = -1e30f, m1 = -1e30f, l0r = 0.f, l1r = 0.f;
    float oacc[8][4] = {};

    int b_roff = lane & 7, b_koff = ((lane >> 3) & 1)*8;

    for (int it = 0; it < 16; it++) {
        if (it) { CP_WAIT1(); __syncthreads(); }
        uint32_t kbuf = kb + (it & 1)*9216;
        uint32_t vbuf = vb + (it & 1)*9216;

        unsigned w0a = mrow0[it*2], w0b = mrow0[it*2+1];
        unsigned w1a = mrow1[it*2], w1b = mrow1[it*2+1];

        float sacc[8][4] = {};
#pragma unroll
        for (int ks = 0; ks < 4; ks++) {
#pragma unroll
            for (int nf = 0; nf < 8; nf++) {
                uint32_t bf[2];
                LDSM_X2(bf, kbuf + (nf*8 + b_roff)*FH + (ks*16 + b_koff)*2);
                MMA16816(sacc[nf], qf[ks], bf[0], bf[1]);
            }
        }

        float mx0 = -1e30f, mx1 = -1e30f;
#pragma unroll
        for (int nf = 0; nf < 8; nf++) {
            int c0 = nf*8 + bq*2, c1 = c0 + 1;
            unsigned m0w = (c0 < 32) ? w0a : w0b;
            unsigned m1w = (c0 < 32) ? w1a : w1b;
            float s0 = sacc[nf][0]*SCALE2; if ((m0w >> (c0 & 31)) & 1u) s0 = -1e9f;
            float s1 = sacc[nf][1]*SCALE2; if ((m0w >> (c1 & 31)) & 1u) s1 = -1e9f;
            float s2 = sacc[nf][2]*SCALE2; if ((m1w >> (c0 & 31)) & 1u) s2 = -1e9f;
            float s3 = sacc[nf][3]*SCALE2; if ((m1w >> (c1 & 31)) & 1u) s3 = -1e9f;
            sacc[nf][0] = s0; sacc[nf][1] = s1; sacc[nf][2] = s2; sacc[nf][3] = s3;
            mx0 = fmaxf(mx0, fmaxf(s0, s1));
            mx1 = fmaxf(mx1, fmaxf(s2, s3));
        }
        mx0 = fmaxf(mx0, __shfl_xor_sync(0xffffffffu, mx0, 1));
        mx0 = fmaxf(mx0, __shfl_xor_sync(0xffffffffu, mx0, 2));
        mx1 = fmaxf(mx1, __shfl_xor_sync(0xffffffffu, mx1, 1));
        mx1 = fmaxf(mx1, __shfl_xor_sync(0xffffffffu, mx1, 2));

        float mn0 = fmaxf(m0, mx0), mn1 = fmaxf(m1, mx1);
        float a0 = fexp2(m0 - mn0), a1 = fexp2(m1 - mn1);
        m0 = mn0; m1 = mn1;

        float ps0 = 0.f, ps1 = 0.f;
        uint32_t pf[8][2];
#pragma unroll
        for (int nf = 0; nf < 8; nf++) {
            float p0 = fexp2(sacc[nf][0] - mn0);
            float p1 = fexp2(sacc[nf][1] - mn0);
            float p2 = fexp2(sacc[nf][2] - mn1);
            float p3 = fexp2(sacc[nf][3] - mn1);
            ps0 += p0 + p1; ps1 += p2 + p3;
            __half2 h01 = __floats2half2_rn(p0, p1);
            __half2 h23 = __floats2half2_rn(p2, p3);
            pf[nf][0] = *(uint32_t*)&h01;
            pf[nf][1] = *(uint32_t*)&h23;
        }
        l0r = l0r*a0 + ps0;
        l1r = l1r*a1 + ps1;
#pragma unroll
        for (int nf = 0; nf < 8; nf++) {
            oacc[nf][0] *= a0; oacc[nf][1] *= a0;
            oacc[nf][2] *= a1; oacc[nf][3] *= a1;
        }

#pragma unroll
        for (int ks = 0; ks < 4; ks++) {
            uint32_t ap[4] = { pf[2*ks][0], pf[2*ks][1], pf[2*ks+1][0], pf[2*ks+1][1] };
#pragma unroll
            for (int nf = 0; nf < 8; nf++) {
                uint32_t bf[2];
                LDSM_X2T(bf, vbuf + (ks*16 + b_roff + b_koff)*FH + nf*16);
                MMA16816(oacc[nf], ap, bf[0], bf[1]);
            }
        }
        __syncthreads();
        int nt = it + 2;
        if (nt < 16) {
            uint32_t kd = kb + (it & 1)*9216, vd = vb + (it & 1)*9216;
#pragma unroll
            for (int i = 0; i < 4; i++) {
                int e = tid + i*128, r = e >> 3, c = e & 7;
                cp16(kd + r*FH + c*16, Kp0 + (size_t)(nt*64 + r)*LDQ + c*8);
                cp16(vd + r*FH + c*16, Vp0 + (size_t)(nt*64 + r)*LDQ + c*8);
            }
        }
        CP_COMMIT();
    }

    l0r += __shfl_xor_sync(0xffffffffu, l0r, 1);
    l0r += __shfl_xor_sync(0xffffffffu, l0r, 2);
    l1r += __shfl_xor_sync(0xffffffffu, l1r, 1);
    l1r += __shfl_xor_sync(0xffffffffu, l1r, 2);
    float inv0 = l0r > 0.f ? 1.0f/l0r : 0.f;
    float inv1 = l1r > 0.f ? 1.0f/l1r : 0.f;

    __half* Cp = C + ((size_t)(b*L + l0 + r0loc))*D + hh*DQ;
#pragma unroll
    for (int nf = 0; nf < 8; nf++) {
        int c0 = nf*8 + bq*2;
        *(__half2*)(Cp + c0)        = __floats2half2_rn(oacc[nf][0]*inv0, oacc[nf][1]*inv0);
        *(__half2*)(Cp + 8*D + c0)  = __floats2half2_rn(oacc[nf][2]*inv1, oacc[nf][3]*inv1);
    }
}

// ================= residual + layernorm (fp32 + fp16 mirror) ================
__global__ void addln_kernel(float* __restrict__ h, const float* __restrict__ t,
                             const float* __restrict__ gamma, const float* __restrict__ beta) {
    int row = blockIdx.x;
    int tid = threadIdx.x;
    float* hr = h + (size_t)row*D;
    __half* hr16 = g_h16 + (size_t)row*D;
    const float* tr = t + (size_t)row*D;
    float v[4]; float sum = 0.f, sq = 0.f;
#pragma unroll
    for (int i = 0; i < 4; i++) {
        int c = tid + i*256;
        float x = hr[c] + tr[c];
        v[i] = x; sum += x; sq += x*x;
    }
#pragma unroll
    for (int o = 16; o; o >>= 1) {
        sum += __shfl_xor_sync(0xffffffffu, sum, o);
        sq  += __shfl_xor_sync(0xffffffffu, sq,  o);
    }
    __shared__ float s1[8], s2[8];
    int warp = tid >> 5, lane = tid & 31;
    if (lane == 0) { s1[warp] = sum; s2[warp] = sq; }
    __syncthreads();
    float ts = 0.f, tq = 0.f;
#pragma unroll
    for (int i = 0; i < 8; i++) { ts += s1[i]; tq += s2[i]; }
    float mean = ts * (1.0f/D);
    float var  = tq * (1.0f/D) - mean*mean;
    float rstd = rsqrtf(var + 1e-5f);
#pragma unroll
    for (int i = 0; i < 4; i++) {
        int c = tid + i*256;
        float r = (v[i] - mean)*rstd*gamma[c] + beta[c];
        hr[c] = r;
        hr16[c] = __float2half(r);
    }
}

// ================= layer-6 small path (8 last-token rows) ===================
__global__ void wo_small(const __half* __restrict__ ctx, const __half* __restrict__ w,
                         const float* __restrict__ bias) {
    int b = blockIdx.y, n = blockIdx.x*256 + threadIdx.x;
    const __half2* a  = (const __half2*)(ctx + ((size_t)b*L + (L-1))*D);
    const __half2* wp = (const __half2*)(w + (size_t)n*D);
    float acc = 0.f;
#pragma unroll 8
    for (int k = 0; k < D/2; k++) {
        float2 av = __half22float2(a[k]), wv = __half22float2(wp[k]);
        acc += av.x*wv.x + av.y*wv.y;
    }
    g_trow[b*D + n] = acc + bias[n];
}

__global__ void ff1_small(const __half* __restrict__ w, const float* __restrict__ bias) {
    int b = blockIdx.y, n = blockIdx.x*256 + threadIdx.x;
    const __half2* a  = (const __half2*)(g_hrow16 + (size_t)b*D);
    const __half2* wp = (const __half2*)(w + (size_t)n*D);
    float acc = 0.f;
#pragma unroll 8
    for (int k = 0; k < D/2; k++) {
        float2 av = __half22float2(a[k]), wv = __half22float2(wp[k]);
        acc += av.x*wv.x + av.y*wv.y;
    }
    g_frow16[(size_t)b*DFF + n] = __float2half(fmaxf(acc + bias[n], 0.f));
}

__global__ void ff2_small(const __half* __restrict__ w, const float* __restrict__ bias) {
    int b = blockIdx.y, n = blockIdx.x*256 + threadIdx.x;
    const __half2* a  = (const __half2*)(g_frow16 + (size_t)b*DFF);
    const __half2* wp = (const __half2*)(w + (size_t)n*DFF);
    float acc = 0.f;
#pragma unroll 8
    for (int k = 0; k < DFF/2; k++) {
        float2 av = __half22float2(a[k]), wv = __half22float2(wp[k]);
        acc += av.x*wv.x + av.y*wv.y;
    }
    g_trow[b*D + n] = acc + bias[n];
}

__global__ void addln_small(const float* __restrict__ hbig,
                            const float* __restrict__ gamma, const float* __restrict__ beta,
                            int hsel) {
    int b = blockIdx.x, tid = threadIdx.x;
    const float* hr = hsel ? (g_hrow + (size_t)b*D)
                           : (hbig + ((size_t)b*L + (L-1))*D);
    const float* tr = g_trow + (size_t)b*D;
    float v[4]; float sum = 0.f, sq = 0.f;
#pragma unroll
    for (int i = 0; i < 4; i++) {
        int c = tid + i*256;
        float x = hr[c] + tr[c];
        v[i] = x; sum += x; sq += x*x;
    }
#pragma unroll
    for (int o = 16; o; o >>= 1) {
        sum += __shfl_xor_sync(0xffffffffu, sum, o);
        sq  += __shfl_xor_sync(0xffffffffu, sq,  o);
    }
    __shared__ float s1[8], s2[8];
    int warp = tid >> 5, lane = tid & 31;
    if (lane == 0) { s1[warp] = sum; s2[warp] = sq; }
    __syncthreads();
    float ts = 0.f, tq = 0.f;
#pragma unroll
    for (int i = 0; i < 8; i++) { ts += s1[i]; tq += s2[i]; }
    float mean = ts * (1.0f/D);
    float var  = tq * (1.0f/D) - mean*mean;
    float rstd = rsqrtf(var + 1e-5f);
#pragma unroll
    for (int i = 0; i < 4; i++) {
        int c = tid + i*256;
        float r = (v[i] - mean)*rstd*gamma[c] + beta[c];
        if (hsel) g_hfin[b*D + c] = r;
        else { g_hrow[b*D + c] = r; g_hrow16[b*D + c] = __float2half(r); }
    }
}

// ================= final logits + log-softmax ===============================
__global__ void final_kernel(const float* __restrict__ ow, const float* __restrict__ ob,
                             float* __restrict__ out) {
    int b = blockIdx.x;
    const float* hr = g_hfin + (size_t)b*D;
    int a = threadIdx.x >> 5, lane = threadIdx.x & 31;
    float s = 0.f;
    for (int c = lane; c < D; c += 32) s += hr[c] * ow[c*16 + a];
#pragma unroll
    for (int o = 16; o; o >>= 1) s += __shfl_down_sync(0xffffffffu, s, o);
    __shared__ float lg[16];
    if (lane == 0) lg[a] = s + ob[a];
    __syncthreads();
    if (threadIdx.x == 0) {
        float mx = lg[0];
#pragma unroll
        for (int i = 1; i < 16; i++) mx = fmaxf(mx, lg[i]);
        float sum = 0.f;
#pragma unroll
        for (int i = 0; i < 16; i++) sum += expf(lg[i] - mx);
        float lse = mx + logf(sum);
#pragma unroll
        for (int i = 0; i < 16; i++) out[b*16 + i] = lg[i] - lse;
    }
}

// ================= launch ====================================================
extern "C" void kernel_launch(void* const* d_in, const int* in_sizes, int n_in,
                              void* d_out, int out_size) {
    const int*   x     = (const int*)  d_in[0];
    const int*   mask  = (const int*)  d_in[1];
    const float* embed = (const float*)d_in[2];
    const float* Wq    = (const float*)d_in[3];
    const float* Wk    = (const float*)d_in[4];
    const float* Wv    = (const float*)d_in[5];
    const float* Wo_w  = (const float*)d_in[6];
    const float* Wo_b  = (const float*)d_in[7];
    const float* ln1_s = (const float*)d_in[8];
    const float* ln1_b = (const float*)d_in[9];
    const float* ff_w1 = (const float*)d_in[10];
    const float* ff_b1 = (const float*)d_in[11];
    const float* ff_w2 = (const float*)d_in[12];
    const float* ff_b2 = (const float*)d_in[13];
    const float* ln2_s = (const float*)d_in[14];
    const float* ln2_b = (const float*)d_in[15];
    const float* out_w = (const float*)d_in[16];
    const float* out_b = (const float*)d_in[17];
    float* out = (float*)d_out;

    float *ph, *pt;
    __half *ph16, *pqkv16, *pctx16, *pff16, *pwqkv, *pwo, *pw1, *pw2;
    cudaGetSymbolAddress((void**)&ph,  g_h);
    cudaGetSymbolAddress((void**)&pt,  g_t);
    cudaGetSymbolAddress((void**)&ph16,   g_h16);
    cudaGetSymbolAddress((void**)&pqkv16, g_qkv16);
    cudaGetSymbolAddress((void**)&pctx16, g_ctx16);
    cudaGetSymbolAddress((void**)&pff16,  g_ff16);
    cudaGetSymbolAddress((void**)&pwqkv, g_wqkv16);
    cudaGetSymbolAddress((void**)&pwo,  g_wo16);
    cudaGetSymbolAddress((void**)&pw1,  g_w116);
    cudaGetSymbolAddress((void**)&pw2,  g_w216);

    cudaFuncSetAttribute(gemm_mma<false,false,1>, cudaFuncAttributeMaxDynamicSharedMemorySize, GEMM_SMEM);
    cudaFuncSetAttribute(gemm_mma<true,false,0>,  cudaFuncAttributeMaxDynamicSharedMemorySize, GEMM_SMEM);
    cudaFuncSetAttribute(gemm_mma<true,true,1>,   cudaFuncAttributeMaxDynamicSharedMemorySize, GEMM_SMEM);

    invdiv_kernel<<<1, 512>>>();
    pe_kernel<<<(L*(D/2))/256, 256>>>();
    mbits_kernel<<<(BATCH*L*(L/32))/256, 256>>>(mask);
    embed_kernel<<<MROWS, 256>>>(x, embed);

    dim3 tb(32, 8);
    wtr_qkv<<<dim3(2, 32, NLAYERS*H), tb>>>(Wq, pwqkv, 0);
    wtr_qkv<<<dim3(2, 32, NLAYERS*H), tb>>>(Wk, pwqkv, 1);
    wtr_qkv<<<dim3(2, 32, NLAYERS*H), tb>>>(Wv, pwqkv, 2);
    wtr_kernel<<<dim3(32, 32, NLAYERS), tb>>>(Wo_w, pwo, 1024, 1024);
    wtr_kernel<<<dim3(128, 32, NLAYERS), tb>>>(ff_w1, pw1, 1024, 4096);
    wtr_kernel<<<dim3(32, 128, NLAYERS), tb>>>(ff_w2, pw2, 4096, 1024);

    // persistent tiling: tilesX, nTiles per GEMM shape
    const int txQKV = 3072/GBN, ntQKV = txQKV * (MROWS/GBM);   // 24, 1536
    const int txD   = D/GBN,    ntD   = txD   * (MROWS/GBM);   // 8, 512
    const int txF   = DFF/GBN,  ntF   = txF   * (MROWS/GBM);   // 32, 2048
    for (int i = 0; i < NLAYERS; i++) {
        int last = (i == NLAYERS-1);
        size_t wOff = (size_t)i*D*D, fOff = (size_t)i*DFF*D;
        gemm_mma<false,false,1><<<NPERS, 256, GEMM_SMEM>>>(
            ph16, pwqkv + (size_t)i*3072*1024, nullptr, pqkv16, D, 3072, txQKV, ntQKV, last);

        if (!last) {
            flash_mma<<<dim3(16, BATCH*H), 128>>>(pqkv16, pctx16, 0);
            gemm_mma<true,false,0><<<NPERS, 256, GEMM_SMEM>>>(
                pctx16, pwo + wOff, Wo_b + (size_t)i*D, pt, D, D, txD, ntD, 0);
            addln_kernel<<<MROWS, 256>>>(ph, pt, ln1_s + (size_t)i*D, ln1_b + (size_t)i*D);
            gemm_mma<true,true,1><<<NPERS, 256, GEMM_SMEM>>>(
                ph16, pw1 + fOff, ff_b1 + (size_t)i*DFF, pff16, D, DFF, txF, ntF, 0);
            gemm_mma<true,false,0><<<NPERS, 256, GEMM_SMEM>>>(
                pff16, pw2 + fOff, ff_b2 + (size_t)i*D, pt, DFF, D, txD, ntD, 0);
            addln_kernel<<<MROWS, 256>>>(ph, pt, ln2_s + (size_t)i*D, ln2_b + (size_t)i*D);
        } else {
            flash_mma<<<dim3(1, BATCH*H), 128>>>(pqkv16, pctx16, 960);
            wo_small<<<dim3(4, 8), 256>>>(pctx16, pwo + wOff, Wo_b + (size_t)i*D);
            addln_small<<<8, 256>>>(ph, ln1_s + (size_t)i*D, ln1_b + (size_t)i*D, 0);
            ff1_small<<<dim3(16, 8), 256>>>(pw1 + fOff, ff_b1 + (size_t)i*DFF);
            ff2_small<<<dim3(4, 8), 256>>>(pw2 + fOff, ff_b2 + (size_t)i*D);
            addln_small<<<8, 256>>>(ph, ln2_s + (size_t)i*D, ln2_b + (size_t)i*D, 1);
        }
    }
    final_kernel<<<BATCH, 512>>>(out_w, out_b, out);
}

// round 15
// speedup vs baseline: 1.0726x; 1.0726x over previous
#include <cuda_runtime.h>
#include <cuda_fp16.h>
#include <math.h>
#include <stdint.h>

#define BATCH   8
#define L       1024
#define D       1024
#define H       16
#define DQ      64
#define DFF     4096
#define NLAYERS 6
#define MROWS   (BATCH*L)   // 8192

// ================= scratch (static device globals) ==========================
__device__ float        g_pe[L*D];
__device__ double       g_invdiv[D/2];
__device__ unsigned int g_mbits[BATCH*L*(L/32)];
__device__ float        g_h[MROWS*D];
__device__ __half       g_t16[(size_t)MROWS*D];
__device__ __half       g_h16[(size_t)MROWS*D];
__device__ __half       g_qkv16[(size_t)MROWS*3072];
__device__ __half       g_ctx16[(size_t)MROWS*D];
__device__ __half       g_ff16[(size_t)MROWS*DFF];
// packed transposed fp16 weights
__device__ __half       g_wqkv16[(size_t)NLAYERS*3072*1024];
__device__ __half       g_wo16[(size_t)NLAYERS*D*D];
__device__ __half       g_w116[(size_t)NLAYERS*DFF*D];
__device__ __half       g_w216[(size_t)NLAYERS*D*DFF];
// layer-6 small-path buffers (8 last-token rows)
__device__ float        g_trow[8*D];
__device__ float        g_hrow[8*D];
__device__ __half       g_hrow16[8*D];
__device__ __half       g_frow16[8*DFF];
__device__ float        g_hfin[8*D];

// ================= ptx helpers ==============================================
__device__ __forceinline__ uint32_t smem_u32(const void* p) {
    uint32_t a;
    asm("{ .reg .u64 t; cvta.to.shared.u64 t, %1; cvt.u32.u64 %0, t; }" : "=r"(a) : "l"(p));
    return a;
}
__device__ __forceinline__ void cp16(uint32_t dst, const void* src) {
    asm volatile("cp.async.cg.shared.global [%0], [%1], 16;" :: "r"(dst), "l"(src) : "memory");
}
#define CP_COMMIT() asm volatile("cp.async.commit_group;" ::: "memory")
#define CP_WAIT1()  asm volatile("cp.async.wait_group 1;" ::: "memory")
#define CP_WAIT0()  asm volatile("cp.async.wait_group 0;" ::: "memory")

#define LDSM_X4(R, a) \
    asm volatile("ldmatrix.sync.aligned.m8n8.x4.shared.b16 {%0,%1,%2,%3}, [%4];" \
        : "=r"((R)[0]), "=r"((R)[1]), "=r"((R)[2]), "=r"((R)[3]) : "r"(a))
#define LDSM_X2(R, a) \
    asm volatile("ldmatrix.sync.aligned.m8n8.x2.shared.b16 {%0,%1}, [%2];" \
        : "=r"((R)[0]), "=r"((R)[1]) : "r"(a))
#define LDSM_X2T(R, a) \
    asm volatile("ldmatrix.sync.aligned.m8n8.x2.trans.shared.b16 {%0,%1}, [%2];" \
        : "=r"((R)[0]), "=r"((R)[1]) : "r"(a))
#define MMA16816(C, A, B0, B1) \
    asm volatile("mma.sync.aligned.m16n8k16.row.col.f32.f16.f16.f32 " \
        "{%0,%1,%2,%3}, {%4,%5,%6,%7}, {%8,%9}, {%0,%1,%2,%3};" \
        : "+f"((C)[0]), "+f"((C)[1]), "+f"((C)[2]), "+f"((C)[3]) \
        : "r"((A)[0]), "r"((A)[1]), "r"((A)[2]), "r"((A)[3]), "r"(B0), "r"(B1))

// fast 2^y for y <= 0 (FMA-pipe only, no MUFU)
__device__ __forceinline__ float fexp2(float y) {
    y = fmaxf(y, -126.0f);
    float t = y + 12582912.0f;
    int   i = __float_as_int(t);
    float f = y - (t - 12582912.0f);
    float p = 0.00133335581f;
    p = fmaf(p, f, 0.00961812911f);
    p = fmaf(p, f, 0.0555041087f);
    p = fmaf(p, f, 0.240226507f);
    p = fmaf(p, f, 0.693147180f);
    p = fmaf(p, f, 1.0f);
    float sc = __int_as_float((i + (127 - 1262485504)) << 23);
    return sc * p;
}

// ================= small prep kernels =======================================
__global__ void invdiv_kernel() {
    int i = threadIdx.x;
    if (i < D/2) g_invdiv[i] = pow(10000.0, -(2.0*i)/(double)D);
}
__global__ void pe_kernel() {
    int idx = blockIdx.x*256 + threadIdx.x;
    int l = idx >> 9, i = idx & 511;
    const double TWO_PI = 6.283185307179586476925286766559;
    const double INV2PI = 0.15915494309189533576888376337251;
    double ang = (double)(l+1) * g_invdiv[i];
    double r = ang - floor(ang*INV2PI)*TWO_PI;
    float fr = (float)r;
    g_pe[l*D + 2*i]     = sinf(fr);
    g_pe[l*D + 2*i + 1] = cosf(fr);
}
__global__ void mbits_kernel(const int* __restrict__ mask) {
    int idx = blockIdx.x*256 + threadIdx.x;
    const int* p = mask + (size_t)idx * 32;
    unsigned int bits = 0u;
#pragma unroll
    for (int i = 0; i < 32; i++) if (p[i] == 0) bits |= (1u << i);
    g_mbits[idx] = bits;
}
__global__ void embed_kernel(const int* __restrict__ x, const float* __restrict__ emb) {
    int row = blockIdx.x;
    int tid = threadIdx.x;
    int token = x[row];
    int l = row & (L-1);
    const float4* e4 = (const float4*)(emb + (size_t)token*D);
    const float4* p4 = (const float4*)(g_pe + (size_t)l*D);
    float4* h4 = (float4*)(g_h + (size_t)row*D);
    float4 e = e4[tid], p = p4[tid];
    float4 o;
    o.x = e.x*32.0f + p.x; o.y = e.y*32.0f + p.y;
    o.z = e.z*32.0f + p.z; o.w = e.w*32.0f + p.w;
    h4[tid] = o;
    __half* h16 = g_h16 + (size_t)row*D + tid*4;
    h16[0] = __float2half(o.x); h16[1] = __float2half(o.y);
    h16[2] = __float2half(o.z); h16[3] = __float2half(o.w);
}

// transpose + fp32->fp16: generic [K][N] -> [N][K]
__global__ void wtr_kernel(const float* __restrict__ in, __half* __restrict__ out, int K, int N) {
    __shared__ float tile[32][33];
    size_t bs = (size_t)blockIdx.z * K * N;
    int bx = blockIdx.x*32, by = blockIdx.y*32;
    int tx = threadIdx.x, ty = threadIdx.y;
#pragma unroll
    for (int i = 0; i < 32; i += 8)
        tile[ty+i][tx] = in[bs + (size_t)(by+ty+i)*N + bx+tx];
    __syncthreads();
#pragma unroll
    for (int i = 0; i < 32; i += 8)
        out[bs + (size_t)(bx+ty+i)*K + by+tx] = __float2half(tile[tx][ty+i]);
}

// QKV pack: in [layer*16+h][1024][64] -> out [layer][3072 rows][1024]
__global__ void wtr_qkv(const float* __restrict__ in, __half* __restrict__ out, int which) {
    __shared__ float tile[32][33];
    int z = blockIdx.z;
    const float* inp = in + (size_t)z*1024*64;
    __half* outp = out + (size_t)(z >> 4)*3072*1024 + (size_t)which*1024*1024
                       + (size_t)(z & 15)*64*1024;
    int bx = blockIdx.x*32, by = blockIdx.y*32;
    int tx = threadIdx.x, ty = threadIdx.y;
#pragma unroll
    for (int i = 0; i < 32; i += 8)
        tile[ty+i][tx] = inp[(size_t)(by+ty+i)*64 + bx+tx];
    __syncthreads();
#pragma unroll
    for (int i = 0; i < 32; i += 8)
        outp[(size_t)(bx+ty+i)*1024 + by+tx] = __float2half(tile[tx][ty+i]);
}

// ================= HMMA fp16 GEMM: CTA 128x128, warp 64x32, GBK=64, 3-stage =
#define GBM 128
#define GBN 128
#define GBK 64
#define GROWB 144               // 64 halfs (128B) + 16B pad
#define STG  (2*128*GROWB)      // 36864
#define GEMM_SMEM (3*STG)       // 110592

__device__ __forceinline__ void stage_tile(const __half* A, const __half* B, int K,
                                           int m0, int n0, uint32_t sbase, int kc, int s, int tid) {
    uint32_t base = sbase + s*STG;
    int k0 = kc*GBK;
#pragma unroll
    for (int i = 0; i < 4; i++) {          // A: 128 rows x 8 chunks of 16B
        int e = tid + i*256;
        int r = e >> 3, c = e & 7;
        cp16(base + r*GROWB + c*16, A + (size_t)(m0 + r)*K + k0 + c*8);
    }
    uint32_t bb = base + 128*GROWB;
#pragma unroll
    for (int i = 0; i < 4; i++) {          // B: 128 rows x 8 chunks of 16B
        int e = tid + i*256;
        int r = e >> 3, c = e & 7;
        cp16(bb + r*GROWB + c*16, B + (size_t)(n0 + r)*K + k0 + c*8);
    }
}

template<bool BIAS, bool RELU>
__global__ __launch_bounds__(256, 2)
void gemm_mma(const __half* __restrict__ A, const __half* __restrict__ B,
              const float* __restrict__ bias, __half* __restrict__ C, int K, int ldc,
              int qskip) {
    int m0 = blockIdx.y * GBM, n0 = blockIdx.x * GBN;
    // layer-6 shortcut: Q columns only needed for last m-tile of each batch
    if (qskip && n0 < 1024 && ((blockIdx.y & 7) != 7)) return;
    extern __shared__ char smem[];
    uint32_t sb = smem_u32(smem);
    int tid = threadIdx.x, lane = tid & 31, wid = tid >> 5;
    int warpM = wid & 1, warpN = wid >> 1;       // 2 x 4 warps, each 64x32
    int NC = K / GBK;

    float acc[4][4][4] = {};                      // [mf][nf][4]

    stage_tile(A, B, K, m0, n0, sb, 0, 0, tid); CP_COMMIT();
    stage_tile(A, B, K, m0, n0, sb, 1, 1, tid); CP_COMMIT();

    // lane offsets
    int aj = lane >> 3, ar = lane & 7;
    int a_moff = (aj & 1)*8 + ar;                 // A x4 row map
    int a_koff = (aj >> 1)*8;
    int b4_roff = ((lane >> 4) & 1)*8 + ar;       // B x4: pairs of n8 frags
    int b4_koff = ((lane >> 3) & 1)*8;

    for (int kc = 0; kc < NC; kc++) {
        CP_WAIT1();
        __syncthreads();
        int nk = kc + 2;
        if (nk < NC) stage_tile(A, B, K, m0, n0, sb, nk, nk % 3, tid);
        CP_COMMIT();

        uint32_t aBase = sb + (kc % 3)*STG;
        uint32_t bBase = aBase + 128*GROWB;
#pragma unroll
        for (int ks = 0; ks < GBK; ks += 16) {
            uint32_t a[4][4], b[2][4];
#pragma unroll
            for (int mf = 0; mf < 4; mf++) {
                int mrow = warpM*64 + mf*16 + a_moff;
                LDSM_X4(a[mf], aBase + mrow*GROWB + (ks + a_koff)*2);
            }
#pragma unroll
            for (int np = 0; np < 2; np++) {       // pairs of n8 frags
                int nrow = warpN*32 + np*16 + b4_roff;
                LDSM_X4(b[np], bBase + nrow*GROWB + (ks + b4_koff)*2);
            }
#pragma unroll
            for (int mf = 0; mf < 4; mf++) {
#pragma unroll
                for (int np = 0; np < 2; np++) {
                    MMA16816(acc[mf][2*np],   a[mf], b[np][0], b[np][1]);
                    MMA16816(acc[mf][2*np+1], a[mf], b[np][2], b[np][3]);
                }
            }
        }
    }
    CP_WAIT0();

    int rrow = lane >> 2, cpair = (lane & 3)*2;
#pragma unroll
    for (int mf = 0; mf < 4; mf++) {
#pragma unroll
        for (int nf = 0; nf < 4; nf++) {
            int row = m0 + warpM*64 + mf*16 + rrow;
            int col = n0 + warpN*32 + nf*8 + cpair;
            float b0 = 0.f, b1 = 0.f;
            if (BIAS) { b0 = __ldg(bias + col); b1 = __ldg(bias + col + 1); }
            float v0 = acc[mf][nf][0] + b0, v1 = acc[mf][nf][1] + b1;
            float v2 = acc[mf][nf][2] + b0, v3 = acc[mf][nf][3] + b1;
            if (RELU) {
                v0 = fmaxf(v0, 0.f); v1 = fmaxf(v1, 0.f);
                v2 = fmaxf(v2, 0.f); v3 = fmaxf(v3, 0.f);
            }
            *(__half2*)(C + (size_t)row*ldc + col)     = __floats2half2_rn(v0, v1);
            *(__half2*)(C + (size_t)(row+8)*ldc + col) = __floats2half2_rn(v2, v3);
        }
    }
}

// ================= HMMA flash attention (packed QKV, stride 3072) ===========
#define FH 144                        // bytes per smem row (72 halfs)
#define LDQ 3072
#define SCALE2 0.18033688011112042f   // (1/8) * log2(e)

__global__ __launch_bounds__(128)
void flash_mma(const __half* __restrict__ QKV, __half* __restrict__ C, int l0base) {
    __shared__ __half sQ[64*72];
    __shared__ __half sK[2][64*72];
    __shared__ __half sV[2][64*72];

    int tid = threadIdx.x, lane = tid & 31, w = tid >> 5;
    int z = blockIdx.y, b = z >> 4, hh = z & 15;
    int l0 = l0base + blockIdx.x * 64;

    const __half* Qp  = QKV + ((size_t)(b*L + l0))*LDQ + hh*DQ;
    const __half* Kp0 = QKV + ((size_t)(b*L))*LDQ + 1024 + hh*DQ;
    const __half* Vp0 = QKV + ((size_t)(b*L))*LDQ + 2048 + hh*DQ;

    uint32_t qb = smem_u32(sQ), kb = smem_u32(sK), vb = smem_u32(sV);

#pragma unroll
    for (int i = 0; i < 4; i++) {
        int e = tid + i*128, r = e >> 3, c = e & 7;
        cp16(qb + r*FH + c*16, Qp + (size_t)r*LDQ + c*8);
    }
#pragma unroll
    for (int i = 0; i < 4; i++) {
        int e = tid + i*128, r = e >> 3, c = e & 7;
        cp16(kb + r*FH + c*16, Kp0 + (size_t)r*LDQ + c*8);
        cp16(vb + r*FH + c*16, Vp0 + (size_t)r*LDQ + c*8);
    }
    CP_COMMIT();
#pragma unroll
    for (int i = 0; i < 4; i++) {
        int e = tid + i*128, r = e >> 3, c = e & 7;
        cp16(kb + 9216 + r*FH + c*16, Kp0 + (size_t)(64 + r)*LDQ + c*8);
        cp16(vb + 9216 + r*FH + c*16, Vp0 + (size_t)(64 + r)*LDQ + c*8);
    }
    CP_COMMIT();

    CP_WAIT1();
    __syncthreads();

    uint32_t qf[4][4];
    int qrow = w*16 + (lane & 7) + ((lane >> 3) & 1)*8;
    int qk = (lane >> 4)*8;
#pragma unroll
    for (int ks = 0; ks < 4; ks++)
        LDSM_X4(qf[ks], qb + qrow*FH + (ks*16 + qk)*2);

    int r0loc = w*16 + (lane >> 2);
    int bq = lane & 3;
    const unsigned* mrow0 = g_mbits + ((size_t)(b*L + l0 + r0loc))*32;
    const unsigned* mrow1 = mrow0 + 8*32;

    float m0 = -1e30f, m1 = -1e30f, l0r = 0.f, l1r = 0.f;
    float oacc[8][4] = {};

    int b_roff = lane & 7, b_koff = ((lane >> 3) & 1)*8;

    for (int it = 0; it < 16; it++) {
        if (it) { CP_WAIT1(); __syncthreads(); }
        uint32_t kbuf = kb + (it & 1)*9216;
        uint32_t vbuf = vb + (it & 1)*9216;

        unsigned w0a = mrow0[it*2], w0b = mrow0[it*2+1];
        unsigned w1a = mrow1[it*2], w1b = mrow1[it*2+1];

        float sacc[8][4] = {};
#pragma unroll
        for (int ks = 0; ks < 4; ks++) {
#pragma unroll
            for (int nf = 0; nf < 8; nf++) {
                uint32_t bf[2];
                LDSM_X2(bf, kbuf + (nf*8 + b_roff)*FH + (ks*16 + b_koff)*2);
                MMA16816(sacc[nf], qf[ks], bf[0], bf[1]);
            }
        }

        float mx0 = -1e30f, mx1 = -1e30f;
#pragma unroll
        for (int nf = 0; nf < 8; nf++) {
            int c0 = nf*8 + bq*2, c1 = c0 + 1;
            unsigned m0w = (c0 < 32) ? w0a : w0b;
            unsigned m1w = (c0 < 32) ? w1a : w1b;
            float s0 = sacc[nf][0]*SCALE2; if ((m0w >> (c0 & 31)) & 1u) s0 = -1e9f;
            float s1 = sacc[nf][1]*SCALE2; if ((m0w >> (c1 & 31)) & 1u) s1 = -1e9f;
            float s2 = sacc[nf][2]*SCALE2; if ((m1w >> (c0 & 31)) & 1u) s2 = -1e9f;
            float s3 = sacc[nf][3]*SCALE2; if ((m1w >> (c1 & 31)) & 1u) s3 = -1e9f;
            sacc[nf][0] = s0; sacc[nf][1] = s1; sacc[nf][2] = s2; sacc[nf][3] = s3;
            mx0 = fmaxf(mx0, fmaxf(s0, s1));
            mx1 = fmaxf(mx1, fmaxf(s2, s3));
        }
        mx0 = fmaxf(mx0, __shfl_xor_sync(0xffffffffu, mx0, 1));
        mx0 = fmaxf(mx0, __shfl_xor_sync(0xffffffffu, mx0, 2));
        mx1 = fmaxf(mx1, __shfl_xor_sync(0xffffffffu, mx1, 1));
        mx1 = fmaxf(mx1, __shfl_xor_sync(0xffffffffu, mx1, 2));

        float mn0 = fmaxf(m0, mx0), mn1 = fmaxf(m1, mx1);
        float a0 = fexp2(m0 - mn0), a1 = fexp2(m1 - mn1);
        m0 = mn0; m1 = mn1;

        float ps0 = 0.f, ps1 = 0.f;
        uint32_t pf[8][2];
#pragma unroll
        for (int nf = 0; nf < 8; nf++) {
            float p0 = fexp2(sacc[nf][0] - mn0);
            float p1 = fexp2(sacc[nf][1] - mn0);
            float p2 = fexp2(sacc[nf][2] - mn1);
            float p3 = fexp2(sacc[nf][3] - mn1);
            ps0 += p0 + p1; ps1 += p2 + p3;
            __half2 h01 = __floats2half2_rn(p0, p1);
            __half2 h23 = __floats2half2_rn(p2, p3);
            pf[nf][0] = *(uint32_t*)&h01;
            pf[nf][1] = *(uint32_t*)&h23;
        }
        l0r = l0r*a0 + ps0;
        l1r = l1r*a1 + ps1;
#pragma unroll
        for (int nf = 0; nf < 8; nf++) {
            oacc[nf][0] *= a0; oacc[nf][1] *= a0;
            oacc[nf][2] *= a1; oacc[nf][3] *= a1;
        }

#pragma unroll
        for (int ks = 0; ks < 4; ks++) {
            uint32_t ap[4] = { pf[2*ks][0], pf[2*ks][1], pf[2*ks+1][0], pf[2*ks+1][1] };
#pragma unroll
            for (int nf = 0; nf < 8; nf++) {
                uint32_t bf[2];
                LDSM_X2T(bf, vbuf + (ks*16 + b_roff + b_koff)*FH + nf*16);
                MMA16816(oacc[nf], ap, bf[0], bf[1]);
            }
        }
        __syncthreads();
        int nt = it + 2;
        if (nt < 16) {
            uint32_t kd = kb + (it & 1)*9216, vd = vb + (it & 1)*9216;
#pragma unroll
            for (int i = 0; i < 4; i++) {
                int e = tid + i*128, r = e >> 3, c = e & 7;
                cp16(kd + r*FH + c*16, Kp0 + (size_t)(nt*64 + r)*LDQ + c*8);
                cp16(vd + r*FH + c*16, Vp0 + (size_t)(nt*64 + r)*LDQ + c*8);
            }
        }
        CP_COMMIT();
    }

    l0r += __shfl_xor_sync(0xffffffffu, l0r, 1);
    l0r += __shfl_xor_sync(0xffffffffu, l0r, 2);
    l1r += __shfl_xor_sync(0xffffffffu, l1r, 1);
    l1r += __shfl_xor_sync(0xffffffffu, l1r, 2);
    float inv0 = l0r > 0.f ? 1.0f/l0r : 0.f;
    float inv1 = l1r > 0.f ? 1.0f/l1r : 0.f;

    __half* Cp = C + ((size_t)(b*L + l0 + r0loc))*D + hh*DQ;
#pragma unroll
    for (int nf = 0; nf < 8; nf++) {
        int c0 = nf*8 + bq*2;
        *(__half2*)(Cp + c0)        = __floats2half2_rn(oacc[nf][0]*inv0, oacc[nf][1]*inv0);
        *(__half2*)(Cp + 8*D + c0)  = __floats2half2_rn(oacc[nf][2]*inv1, oacc[nf][3]*inv1);
    }
}

// ================= residual + layernorm (fp16 t, fp32 h + fp16 mirror) ======
__global__ void addln_kernel(float* __restrict__ h, const __half* __restrict__ t,
                             const float* __restrict__ gamma, const float* __restrict__ beta) {
    int row = blockIdx.x;
    int tid = threadIdx.x;
    float* hr = h + (size_t)row*D;
    __half2* hr16 = (__half2*)(g_h16 + (size_t)row*D);
    const __half2* tr = (const __half2*)(t + (size_t)row*D);
    float2 v[2]; float sum = 0.f, sq = 0.f;
#pragma unroll
    for (int i = 0; i < 2; i++) {
        int p = tid + i*256;                    // pair index 0..511
        float2 hv = *(float2*)&hr[p*2];
        float2 tv = __half22float2(tr[p]);
        float x0 = hv.x + tv.x, x1 = hv.y + tv.y;
        v[i].x = x0; v[i].y = x1;
        sum += x0 + x1; sq += x0*x0 + x1*x1;
    }
#pragma unroll
    for (int o = 16; o; o >>= 1) {
        sum += __shfl_xor_sync(0xffffffffu, sum, o);
        sq  += __shfl_xor_sync(0xffffffffu, sq,  o);
    }
    __shared__ float s1[8], s2[8];
    int warp = tid >> 5, lane = tid & 31;
    if (lane == 0) { s1[warp] = sum; s2[warp] = sq; }
    __syncthreads();
    float ts = 0.f, tq = 0.f;
#pragma unroll
    for (int i = 0; i < 8; i++) { ts += s1[i]; tq += s2[i]; }
    float mean = ts * (1.0f/D);
    float var  = tq * (1.0f/D) - mean*mean;
    float rstd = rsqrtf(var + 1e-5f);
#pragma unroll
    for (int i = 0; i < 2; i++) {
        int p = tid + i*256;
        float r0 = (v[i].x - mean)*rstd*gamma[p*2]   + beta[p*2];
        float r1 = (v[i].y - mean)*rstd*gamma[p*2+1] + beta[p*2+1];
        *(float2*)&hr[p*2] = make_float2(r0, r1);
        hr16[p] = __floats2half2_rn(r0, r1);
    }
}

// ================= layer-6 small path (8 last-token rows) ===================
__global__ void wo_small(const __half* __restrict__ ctx, const __half* __restrict__ w,
                         const float* __restrict__ bias) {
    int b = blockIdx.y, n = blockIdx.x*256 + threadIdx.x;
    const __half2* a  = (const __half2*)(ctx + ((size_t)b*L + (L-1))*D);
    const __half2* wp = (const __half2*)(w + (size_t)n*D);
    float acc = 0.f;
#pragma unroll 8
    for (int k = 0; k < D/2; k++) {
        float2 av = __half22float2(a[k]), wv = __half22float2(wp[k]);
        acc += av.x*wv.x + av.y*wv.y;
    }
    g_trow[b*D + n] = acc + bias[n];
}

__global__ void ff1_small(const __half* __restrict__ w, const float* __restrict__ bias) {
    int b = blockIdx.y, n = blockIdx.x*256 + threadIdx.x;
    const __half2* a  = (const __half2*)(g_hrow16 + (size_t)b*D);
    const __half2* wp = (const __half2*)(w + (size_t)n*D);
    float acc = 0.f;
#pragma unroll 8
    for (int k = 0; k < D/2; k++) {
        float2 av = __half22float2(a[k]), wv = __half22float2(wp[k]);
        acc += av.x*wv.x + av.y*wv.y;
    }
    g_frow16[(size_t)b*DFF + n] = __float2half(fmaxf(acc + bias[n], 0.f));
}

__global__ void ff2_small(const __half* __restrict__ w, const float* __restrict__ bias) {
    int b = blockIdx.y, n = blockIdx.x*256 + threadIdx.x;
    const __half2* a  = (const __half2*)(g_frow16 + (size_t)b*DFF);
    const __half2* wp = (const __half2*)(w + (size_t)n*DFF);
    float acc = 0.f;
#pragma unroll 8
    for (int k = 0; k < DFF/2; k++) {
        float2 av = __half22float2(a[k]), wv = __half22float2(wp[k]);
        acc += av.x*wv.x + av.y*wv.y;
    }
    g_trow[b*D + n] = acc + bias[n];
}

__global__ void addln_small(const float* __restrict__ hbig,
                            const float* __restrict__ gamma, const float* __restrict__ beta,
                            int hsel) {
    int b = blockIdx.x, tid = threadIdx.x;
    const float* hr = hsel ? (g_hrow + (size_t)b*D)
                           : (hbig + ((size_t)b*L + (L-1))*D);
    const float* tr = g_trow + (size_t)b*D;
    float v[4]; float sum = 0.f, sq = 0.f;
#pragma unroll
    for (int i = 0; i < 4; i++) {
        int c = tid + i*256;
        float x = hr[c] + tr[c];
        v[i] = x; sum += x; sq += x*x;
    }
#pragma unroll
    for (int o = 16; o; o >>= 1) {
        sum += __shfl_xor_sync(0xffffffffu, sum, o);
        sq  += __shfl_xor_sync(0xffffffffu, sq,  o);
    }
    __shared__ float s1[8], s2[8];
    int warp = tid >> 5, lane = tid & 31;
    if (lane == 0) { s1[warp] = sum; s2[warp] = sq; }
    __syncthreads();
    float ts = 0.f, tq = 0.f;
#pragma unroll
    for (int i = 0; i < 8; i++) { ts += s1[i]; tq += s2[i]; }
    float mean = ts * (1.0f/D);
    float var  = tq * (1.0f/D) - mean*mean;
    float rstd = rsqrtf(var + 1e-5f);
#pragma unroll
    for (int i = 0; i < 4; i++) {
        int c = tid + i*256;
        float r = (v[i] - mean)*rstd*gamma[c] + beta[c];
        if (hsel) g_hfin[b*D + c] = r;
        else { g_hrow[b*D + c] = r; g_hrow16[b*D + c] = __float2half(r); }
    }
}

// ================= final logits + log-softmax ===============================
__global__ void final_kernel(const float* __restrict__ ow, const float* __restrict__ ob,
                             float* __restrict__ out) {
    int b = blockIdx.x;
    const float* hr = g_hfin + (size_t)b*D;
    int a = threadIdx.x >> 5, lane = threadIdx.x & 31;
    float s = 0.f;
    for (int c = lane; c < D; c += 32) s += hr[c] * ow[c*16 + a];
#pragma unroll
    for (int o = 16; o; o >>= 1) s += __shfl_down_sync(0xffffffffu, s, o);
    __shared__ float lg[16];
    if (lane == 0) lg[a] = s + ob[a];
    __syncthreads();
    if (threadIdx.x == 0) {
        float mx = lg[0];
#pragma unroll
        for (int i = 1; i < 16; i++) mx = fmaxf(mx, lg[i]);
        float sum = 0.f;
#pragma unroll
        for (int i = 0; i < 16; i++) sum += expf(lg[i] - mx);
        float lse = mx + logf(sum);
#pragma unroll
        for (int i = 0; i < 16; i++) out[b*16 + i] = lg[i] - lse;
    }
}

// ================= launch ====================================================
extern "C" void kernel_launch(void* const* d_in, const int* in_sizes, int n_in,
                              void* d_out, int out_size) {
    const int*   x     = (const int*)  d_in[0];
    const int*   mask  = (const int*)  d_in[1];
    const float* embed = (const float*)d_in[2];
    const float* Wq    = (const float*)d_in[3];
    const float* Wk    = (const float*)d_in[4];
    const float* Wv    = (const float*)d_in[5];
    const float* Wo_w  = (const float*)d_in[6];
    const float* Wo_b  = (const float*)d_in[7];
    const float* ln1_s = (const float*)d_in[8];
    const float* ln1_b = (const float*)d_in[9];
    const float* ff_w1 = (const float*)d_in[10];
    const float* ff_b1 = (const float*)d_in[11];
    const float* ff_w2 = (const float*)d_in[12];
    const float* ff_b2 = (const float*)d_in[13];
    const float* ln2_s = (const float*)d_in[14];
    const float* ln2_b = (const float*)d_in[15];
    const float* out_w = (const float*)d_in[16];
    const float* out_b = (const float*)d_in[17];
    float* out = (float*)d_out;

    float *ph;
    __half *pt16, *ph16, *pqkv16, *pctx16, *pff16, *pwqkv, *pwo, *pw1, *pw2;
    cudaGetSymbolAddress((void**)&ph,   g_h);
    cudaGetSymbolAddress((void**)&pt16, g_t16);
    cudaGetSymbolAddress((void**)&ph16,   g_h16);
    cudaGetSymbolAddress((void**)&pqkv16, g_qkv16);
    cudaGetSymbolAddress((void**)&pctx16, g_ctx16);
    cudaGetSymbolAddress((void**)&pff16,  g_ff16);
    cudaGetSymbolAddress((void**)&pwqkv, g_wqkv16);
    cudaGetSymbolAddress((void**)&pwo,  g_wo16);
    cudaGetSymbolAddress((void**)&pw1,  g_w116);
    cudaGetSymbolAddress((void**)&pw2,  g_w216);

    cudaFuncSetAttribute(gemm_mma<false,false>, cudaFuncAttributeMaxDynamicSharedMemorySize, GEMM_SMEM);
    cudaFuncSetAttribute(gemm_mma<true,false>,  cudaFuncAttributeMaxDynamicSharedMemorySize, GEMM_SMEM);
    cudaFuncSetAttribute(gemm_mma<true,true>,   cudaFuncAttributeMaxDynamicSharedMemorySize, GEMM_SMEM);

    invdiv_kernel<<<1, 512>>>();
    pe_kernel<<<(L*(D/2))/256, 256>>>();
    mbits_kernel<<<(BATCH*L*(L/32))/256, 256>>>(mask);
    embed_kernel<<<MROWS, 256>>>(x, embed);

    dim3 tb(32, 8);
    wtr_qkv<<<dim3(2, 32, NLAYERS*H), tb>>>(Wq, pwqkv, 0);
    wtr_qkv<<<dim3(2, 32, NLAYERS*H), tb>>>(Wk, pwqkv, 1);
    wtr_qkv<<<dim3(2, 32, NLAYERS*H), tb>>>(Wv, pwqkv, 2);
    wtr_kernel<<<dim3(32, 32, NLAYERS), tb>>>(Wo_w, pwo, 1024, 1024);
    wtr_kernel<<<dim3(128, 32, NLAYERS), tb>>>(ff_w1, pw1, 1024, 4096);
    wtr_kernel<<<dim3(32, 128, NLAYERS), tb>>>(ff_w2, pw2, 4096, 1024);

    dim3 gQKV(3072/GBN, MROWS/GBM);   // (24, 64)
    dim3 gD(D/GBN, MROWS/GBM);        // (8, 64)
    dim3 gF(DFF/GBN, MROWS/GBM);      // (32, 64)
    for (int i = 0; i < NLAYERS; i++) {
        int last = (i == NLAYERS-1);
        size_t wOff = (size_t)i*D*D, fOff = (size_t)i*DFF*D;
        gemm_mma<false,false><<<gQKV, 256, GEMM_SMEM>>>(
            ph16, pwqkv + (size_t)i*3072*1024, nullptr, pqkv16, D, 3072, last);

        if (!last) {
            flash_mma<<<dim3(16, BATCH*H), 128>>>(pqkv16, pctx16, 0);
            gemm_mma<true,false><<<gD, 256, GEMM_SMEM>>>(
                pctx16, pwo + wOff, Wo_b + (size_t)i*D, pt16, D, D, 0);
            addln_kernel<<<MROWS, 256>>>(ph, pt16, ln1_s + (size_t)i*D, ln1_b + (size_t)i*D);
            gemm_mma<true,true><<<gF, 256, GEMM_SMEM>>>(
                ph16, pw1 + fOff, ff_b1 + (size_t)i*DFF, pff16, D, DFF, 0);
            gemm_mma<true,false><<<gD, 256, GEMM_SMEM>>>(
                pff16, pw2 + fOff, ff_b2 + (size_t)i*D, pt16, DFF, D, 0);
            addln_kernel<<<MROWS, 256>>>(ph, pt16, ln2_s + (size_t)i*D, ln2_b + (size_t)i*D);
        } else {
            flash_mma<<<dim3(1, BATCH*H), 128>>>(pqkv16, pctx16, 960);
            wo_small<<<dim3(4, 8), 256>>>(pctx16, pwo + wOff, Wo_b + (size_t)i*D);
            addln_small<<<8, 256>>>(ph, ln1_s + (size_t)i*D, ln1_b + (size_t)i*D, 0);
            ff1_small<<<dim3(16, 8), 256>>>(pw1 + fOff, ff_b1 + (size_t)i*DFF);
            ff2_small<<<dim3(4, 8), 256>>>(pw2 + fOff, ff_b2 + (size_t)i*D);
            addln_small<<<8, 256>>>(ph, ln2_s + (size_t)i*D, ln2_b + (size_t)i*D, 1);
        }
    }
    final_kernel<<<BATCH, 512>>>(out_w, out_b, out);
}

// round 17
// speedup vs baseline: 1.0732x; 1.0006x over previous
#include <cuda_runtime.h>
#include <cuda_fp16.h>
#include <math.h>
#include <stdint.h>

#define BATCH   8
#define L       1024
#define D       1024
#define H       16
#define DQ      64
#define DFF     4096
#define NLAYERS 6
#define MROWS   (BATCH*L)   // 8192

// ================= scratch (static device globals) ==========================
__device__ float        g_pe[L*D];
__device__ double       g_invdiv[D/2];
__device__ unsigned int g_mbits[BATCH*L*(L/32)];
__device__ __half       g_t16[(size_t)MROWS*D];
__device__ __half       g_h16[(size_t)MROWS*D];     // canonical residual stream
__device__ __half       g_qkv16[(size_t)MROWS*3072];
__device__ __half       g_ctx16[(size_t)MROWS*D];
__device__ __half       g_ff16[(size_t)MROWS*DFF];
// packed transposed fp16 weights
__device__ __half       g_wqkv16[(size_t)NLAYERS*3072*1024];
__device__ __half       g_wo16[(size_t)NLAYERS*D*D];
__device__ __half       g_w116[(size_t)NLAYERS*DFF*D];
__device__ __half       g_w216[(size_t)NLAYERS*D*DFF];
// layer-6 small-path buffers (8 last-token rows, fp32 for final precision)
__device__ float        g_trow[8*D];
__device__ float        g_hrow[8*D];
__device__ __half       g_hrow16[8*D];
__device__ __half       g_frow16[8*DFF];
__device__ float        g_hfin[8*D];

// ================= ptx helpers ==============================================
__device__ __forceinline__ uint32_t smem_u32(const void* p) {
    uint32_t a;
    asm("{ .reg .u64 t; cvta.to.shared.u64 t, %1; cvt.u32.u64 %0, t; }" : "=r"(a) : "l"(p));
    return a;
}
__device__ __forceinline__ void cp16(uint32_t dst, const void* src) {
    asm volatile("cp.async.cg.shared.global [%0], [%1], 16;" :: "r"(dst), "l"(src) : "memory");
}
#define CP_COMMIT() asm volatile("cp.async.commit_group;" ::: "memory")
#define CP_WAIT1()  asm volatile("cp.async.wait_group 1;" ::: "memory")
#define CP_WAIT0()  asm volatile("cp.async.wait_group 0;" ::: "memory")

#define LDSM_X4(R, a) \
    asm volatile("ldmatrix.sync.aligned.m8n8.x4.shared.b16 {%0,%1,%2,%3}, [%4];" \
        : "=r"((R)[0]), "=r"((R)[1]), "=r"((R)[2]), "=r"((R)[3]) : "r"(a))
#define LDSM_X2(R, a) \
    asm volatile("ldmatrix.sync.aligned.m8n8.x2.shared.b16 {%0,%1}, [%2];" \
        : "=r"((R)[0]), "=r"((R)[1]) : "r"(a))
#define LDSM_X2T(R, a) \
    asm volatile("ldmatrix.sync.aligned.m8n8.x2.trans.shared.b16 {%0,%1}, [%2];" \
        : "=r"((R)[0]), "=r"((R)[1]) : "r"(a))
#define MMA16816(C, A, B0, B1) \
    asm volatile("mma.sync.aligned.m16n8k16.row.col.f32.f16.f16.f32 " \
        "{%0,%1,%2,%3}, {%4,%5,%6,%7}, {%8,%9}, {%0,%1,%2,%3};" \
        : "+f"((C)[0]), "+f"((C)[1]), "+f"((C)[2]), "+f"((C)[3]) \
        : "r"((A)[0]), "r"((A)[1]), "r"((A)[2]), "r"((A)[3]), "r"(B0), "r"(B1))

// fast 2^y for y <= 0 (FMA-pipe only, no MUFU)
__device__ __forceinline__ float fexp2(float y) {
    y = fmaxf(y, -126.0f);
    float t = y + 12582912.0f;
    int   i = __float_as_int(t);
    float f = y - (t - 12582912.0f);
    float p = 0.00133335581f;
    p = fmaf(p, f, 0.00961812911f);
    p = fmaf(p, f, 0.0555041087f);
    p = fmaf(p, f, 0.240226507f);
    p = fmaf(p, f, 0.693147180f);
    p = fmaf(p, f, 1.0f);
    float sc = __int_as_float((i + (127 - 1262485504)) << 23);
    return sc * p;
}

// ================= small prep kernels =======================================
__global__ void invdiv_kernel() {
    int i = threadIdx.x;
    if (i < D/2) g_invdiv[i] = pow(10000.0, -(2.0*i)/(double)D);
}
__global__ void pe_kernel() {
    int idx = blockIdx.x*256 + threadIdx.x;
    int l = idx >> 9, i = idx & 511;
    const double TWO_PI = 6.283185307179586476925286766559;
    const double INV2PI = 0.15915494309189533576888376337251;
    double ang = (double)(l+1) * g_invdiv[i];
    double r = ang - floor(ang*INV2PI)*TWO_PI;
    float fr = (float)r;
    g_pe[l*D + 2*i]     = sinf(fr);
    g_pe[l*D + 2*i + 1] = cosf(fr);
}
__global__ void mbits_kernel(const int* __restrict__ mask) {
    int idx = blockIdx.x*256 + threadIdx.x;
    const int* p = mask + (size_t)idx * 32;
    unsigned int bits = 0u;
#pragma unroll
    for (int i = 0; i < 32; i++) if (p[i] == 0) bits |= (1u << i);
    g_mbits[idx] = bits;
}
__global__ void embed_kernel(const int* __restrict__ x, const float* __restrict__ emb) {
    int row = blockIdx.x;
    int tid = threadIdx.x;
    int token = x[row];
    int l = row & (L-1);
    const float4* e4 = (const float4*)(emb + (size_t)token*D);
    const float4* p4 = (const float4*)(g_pe + (size_t)l*D);
    float4 e = e4[tid], p = p4[tid];
    __half2* h16 = (__half2*)(g_h16 + (size_t)row*D + tid*4);
    h16[0] = __floats2half2_rn(e.x*32.0f + p.x, e.y*32.0f + p.y);
    h16[1] = __floats2half2_rn(e.z*32.0f + p.z, e.w*32.0f + p.w);
}

// transpose + fp32->fp16: generic [K][N] -> [N][K]
__global__ void wtr_kernel(const float* __restrict__ in, __half* __restrict__ out, int K, int N) {
    __shared__ float tile[32][33];
    size_t bs = (size_t)blockIdx.z * K * N;
    int bx = blockIdx.x*32, by = blockIdx.y*32;
    int tx = threadIdx.x, ty = threadIdx.y;
#pragma unroll
    for (int i = 0; i < 32; i += 8)
        tile[ty+i][tx] = in[bs + (size_t)(by+ty+i)*N + bx+tx];
    __syncthreads();
#pragma unroll
    for (int i = 0; i < 32; i += 8)
        out[bs + (size_t)(bx+ty+i)*K + by+tx] = __float2half(tile[tx][ty+i]);
}

// QKV pack: in [layer*16+h][1024][64] -> out [layer][3072 rows][1024]
__global__ void wtr_qkv(const float* __restrict__ in, __half* __restrict__ out, int which) {
    __shared__ float tile[32][33];
    int z = blockIdx.z;
    const float* inp = in + (size_t)z*1024*64;
    __half* outp = out + (size_t)(z >> 4)*3072*1024 + (size_t)which*1024*1024
                       + (size_t)(z & 15)*64*1024;
    int bx = blockIdx.x*32, by = blockIdx.y*32;
    int tx = threadIdx.x, ty = threadIdx.y;
#pragma unroll
    for (int i = 0; i < 32; i += 8)
        tile[ty+i][tx] = inp[(size_t)(by+ty+i)*64 + bx+tx];
    __syncthreads();
#pragma unroll
    for (int i = 0; i < 32; i += 8)
        outp[(size_t)(bx+ty+i)*1024 + by+tx] = __float2half(tile[tx][ty+i]);
}

// ================= HMMA fp16 GEMM: CTA 128x128, warp 64x32, GBK=64, 3-stage =
#define GBM 128
#define GBN 128
#define GBK 64
#define GROWB 144               // 64 halfs (128B) + 16B pad
#define STG  (2*128*GROWB)      // 36864
#define GEMM_SMEM (3*STG)       // 110592

__device__ __forceinline__ void stage_tile(const __half* A, const __half* B, int K,
                                           int m0, int n0, uint32_t sbase, int kc, int s, int tid) {
    uint32_t base = sbase + s*STG;
    int k0 = kc*GBK;
#pragma unroll
    for (int i = 0; i < 4; i++) {          // A: 128 rows x 8 chunks of 16B
        int e = tid + i*256;
        int r = e >> 3, c = e & 7;
        cp16(base + r*GROWB + c*16, A + (size_t)(m0 + r)*K + k0 + c*8);
    }
    uint32_t bb = base + 128*GROWB;
#pragma unroll
    for (int i = 0; i < 4; i++) {          // B: 128 rows x 8 chunks of 16B
        int e = tid + i*256;
        int r = e >> 3, c = e & 7;
        cp16(bb + r*GROWB + c*16, B + (size_t)(n0 + r)*K + k0 + c*8);
    }
}

template<bool BIAS, bool RELU>
__global__ __launch_bounds__(256, 2)
void gemm_mma(const __half* __restrict__ A, const __half* __restrict__ B,
              const float* __restrict__ bias, __half* __restrict__ C, int K, int ldc,
              int qskip) {
    int m0 = blockIdx.y * GBM, n0 = blockIdx.x * GBN;
    // layer-6 shortcut: Q columns only needed for last m-tile of each batch
    if (qskip && n0 < 1024 && ((blockIdx.y & 7) != 7)) return;
    extern __shared__ char smem[];
    uint32_t sb = smem_u32(smem);
    int tid = threadIdx.x, lane = tid & 31, wid = tid >> 5;
    int warpM = wid & 1, warpN = wid >> 1;       // 2 x 4 warps, each 64x32
    int NC = K / GBK;

    float acc[4][4][4] = {};                      // [mf][nf][4]

    stage_tile(A, B, K, m0, n0, sb, 0, 0, tid); CP_COMMIT();
    stage_tile(A, B, K, m0, n0, sb, 1, 1, tid); CP_COMMIT();

    // lane offsets
    int aj = lane >> 3, ar = lane & 7;
    int a_moff = (aj & 1)*8 + ar;                 // A x4 row map
    int a_koff = (aj >> 1)*8;
    int b4_roff = ((lane >> 4) & 1)*8 + ar;       // B x4: pairs of n8 frags
    int b4_koff = ((lane >> 3) & 1)*8;

    for (int kc = 0; kc < NC; kc++) {
        CP_WAIT1();
        __syncthreads();
        int nk = kc + 2;
        if (nk < NC) stage_tile(A, B, K, m0, n0, sb, nk, nk % 3, tid);
        CP_COMMIT();

        uint32_t aBase = sb + (kc % 3)*STG;
        uint32_t bBase = aBase + 128*GROWB;
#pragma unroll
        for (int ks = 0; ks < GBK; ks += 16) {
            uint32_t a[4][4], b[2][4];
#pragma unroll
            for (int mf = 0; mf < 4; mf++) {
                int mrow = warpM*64 + mf*16 + a_moff;
                LDSM_X4(a[mf], aBase + mrow*GROWB + (ks + a_koff)*2);
            }
#pragma unroll
            for (int np = 0; np < 2; np++) {       // pairs of n8 frags
                int nrow = warpN*32 + np*16 + b4_roff;
                LDSM_X4(b[np], bBase + nrow*GROWB + (ks + b4_koff)*2);
            }
#pragma unroll
            for (int mf = 0; mf < 4; mf++) {
#pragma unroll
                for (int np = 0; np < 2; np++) {
                    MMA16816(acc[mf][2*np],   a[mf], b[np][0], b[np][1]);
                    MMA16816(acc[mf][2*np+1], a[mf], b[np][2], b[np][3]);
                }
            }
        }
    }
    CP_WAIT0();

    int rrow = lane >> 2, cpair = (lane & 3)*2;
#pragma unroll
    for (int mf = 0; mf < 4; mf++) {
#pragma unroll
        for (int nf = 0; nf < 4; nf++) {
            int row = m0 + warpM*64 + mf*16 + rrow;
            int col = n0 + warpN*32 + nf*8 + cpair;
            float b0 = 0.f, b1 = 0.f;
            if (BIAS) { b0 = __ldg(bias + col); b1 = __ldg(bias + col + 1); }
            float v0 = acc[mf][nf][0] + b0, v1 = acc[mf][nf][1] + b1;
            float v2 = acc[mf][nf][2] + b0, v3 = acc[mf][nf][3] + b1;
            if (RELU) {
                v0 = fmaxf(v0, 0.f); v1 = fmaxf(v1, 0.f);
                v2 = fmaxf(v2, 0.f); v3 = fmaxf(v3, 0.f);
            }
            *(__half2*)(C + (size_t)row*ldc + col)     = __floats2half2_rn(v0, v1);
            *(__half2*)(C + (size_t)(row+8)*ldc + col) = __floats2half2_rn(v2, v3);
        }
    }
}

// ================= HMMA flash attention (packed QKV, stride 3072) ===========
#define FH 144                        // bytes per smem row (72 halfs)
#define LDQ 3072
#define SCALE2 0.18033688011112042f   // (1/8) * log2(e)

__global__ __launch_bounds__(128)
void flash_mma(const __half* __restrict__ QKV, __half* __restrict__ C, int l0base) {
    __shared__ __half sQ[64*72];
    __shared__ __half sK[2][64*72];
    __shared__ __half sV[2][64*72];

    int tid = threadIdx.x, lane = tid & 31, w = tid >> 5;
    int z = blockIdx.y, b = z >> 4, hh = z & 15;
    int l0 = l0base + blockIdx.x * 64;

    const __half* Qp  = QKV + ((size_t)(b*L + l0))*LDQ + hh*DQ;
    const __half* Kp0 = QKV + ((size_t)(b*L))*LDQ + 1024 + hh*DQ;
    const __half* Vp0 = QKV + ((size_t)(b*L))*LDQ + 2048 + hh*DQ;

    uint32_t qb = smem_u32(sQ), kb = smem_u32(sK), vb = smem_u32(sV);

#pragma unroll
    for (int i = 0; i < 4; i++) {
        int e = tid + i*128, r = e >> 3, c = e & 7;
        cp16(qb + r*FH + c*16, Qp + (size_t)r*LDQ + c*8);
    }
#pragma unroll
    for (int i = 0; i < 4; i++) {
        int e = tid + i*128, r = e >> 3, c = e & 7;
        cp16(kb + r*FH + c*16, Kp0 + (size_t)r*LDQ + c*8);
        cp16(vb + r*FH + c*16, Vp0 + (size_t)r*LDQ + c*8);
    }
    CP_COMMIT();
#pragma unroll
    for (int i = 0; i < 4; i++) {
        int e = tid + i*128, r = e >> 3, c = e & 7;
        cp16(kb + 9216 + r*FH + c*16, Kp0 + (size_t)(64 + r)*LDQ + c*8);
        cp16(vb + 9216 + r*FH + c*16, Vp0 + (size_t)(64 + r)*LDQ + c*8);
    }
    CP_COMMIT();

    CP_WAIT1();
    __syncthreads();

    uint32_t qf[4][4];
    int qrow = w*16 + (lane & 7) + ((lane >> 3) & 1)*8;
    int qk = (lane >> 4)*8;
#pragma unroll
    for (int ks = 0; ks < 4; ks++)
        LDSM_X4(qf[ks], qb + qrow*FH + (ks*16 + qk)*2);

    int r0loc = w*16 + (lane >> 2);
    int bq = lane & 3;
    const unsigned* mrow0 = g_mbits + ((size_t)(b*L + l0 + r0loc))*32;
    const unsigned* mrow1 = mrow0 + 8*32;

    float m0 = -1e30f, m1 = -1e30f, l0r = 0.f, l1r = 0.f;
    float oacc[8][4] = {};

    int b_roff = lane & 7, b_koff = ((lane >> 3) & 1)*8;

    for (int it = 0; it < 16; it++) {
        if (it) { CP_WAIT1(); __syncthreads(); }
        uint32_t kbuf = kb + (it & 1)*9216;
        uint32_t vbuf = vb + (it & 1)*9216;

        unsigned w0a = mrow0[it*2], w0b = mrow0[it*2+1];
        unsigned w1a = mrow1[it*2], w1b = mrow1[it*2+1];

        float sacc[8][4] = {};
#pragma unroll
        for (int ks = 0; ks < 4; ks++) {
#pragma unroll
            for (int nf = 0; nf < 8; nf++) {
                uint32_t bf[2];
                LDSM_X2(bf, kbuf + (nf*8 + b_roff)*FH + (ks*16 + b_koff)*2);
                MMA16816(sacc[nf], qf[ks], bf[0], bf[1]);
            }
        }

        float mx0 = -1e30f, mx1 = -1e30f;
#pragma unroll
        for (int nf = 0; nf < 8; nf++) {
            int c0 = nf*8 + bq*2, c1 = c0 + 1;
            unsigned m0w = (c0 < 32) ? w0a : w0b;
            unsigned m1w = (c0 < 32) ? w1a : w1b;
            float s0 = sacc[nf][0]*SCALE2; if ((m0w >> (c0 & 31)) & 1u) s0 = -1e9f;
            float s1 = sacc[nf][1]*SCALE2; if ((m0w >> (c1 & 31)) & 1u) s1 = -1e9f;
            float s2 = sacc[nf][2]*SCALE2; if ((m1w >> (c0 & 31)) & 1u) s2 = -1e9f;
            float s3 = sacc[nf][3]*SCALE2; if ((m1w >> (c1 & 31)) & 1u) s3 = -1e9f;
            sacc[nf][0] = s0; sacc[nf][1] = s1; sacc[nf][2] = s2; sacc[nf][3] = s3;
            mx0 = fmaxf(mx0, fmaxf(s0, s1));
            mx1 = fmaxf(mx1, fmaxf(s2, s3));
        }
        mx0 = fmaxf(mx0, __shfl_xor_sync(0xffffffffu, mx0, 1));
        mx0 = fmaxf(mx0, __shfl_xor_sync(0xffffffffu, mx0, 2));
        mx1 = fmaxf(mx1, __shfl_xor_sync(0xffffffffu, mx1, 1));
        mx1 = fmaxf(mx1, __shfl_xor_sync(0xffffffffu, mx1, 2));

        float mn0 = fmaxf(m0, mx0), mn1 = fmaxf(m1, mx1);
        float a0 = fexp2(m0 - mn0), a1 = fexp2(m1 - mn1);
        m0 = mn0; m1 = mn1;

        float ps0 = 0.f, ps1 = 0.f;
        uint32_t pf[8][2];
#pragma unroll
        for (int nf = 0; nf < 8; nf++) {
            float p0 = fexp2(sacc[nf][0] - mn0);
            float p1 = fexp2(sacc[nf][1] - mn0);
            float p2 = fexp2(sacc[nf][2] - mn1);
            float p3 = fexp2(sacc[nf][3] - mn1);
            ps0 += p0 + p1; ps1 += p2 + p3;
            __half2 h01 = __floats2half2_rn(p0, p1);
            __half2 h23 = __floats2half2_rn(p2, p3);
            pf[nf][0] = *(uint32_t*)&h01;
            pf[nf][1] = *(uint32_t*)&h23;
        }
        l0r = l0r*a0 + ps0;
        l1r = l1r*a1 + ps1;
#pragma unroll
        for (int nf = 0; nf < 8; nf++) {
            oacc[nf][0] *= a0; oacc[nf][1] *= a0;
            oacc[nf][2] *= a1; oacc[nf][3] *= a1;
        }

#pragma unroll
        for (int ks = 0; ks < 4; ks++) {
            uint32_t ap[4] = { pf[2*ks][0], pf[2*ks][1], pf[2*ks+1][0], pf[2*ks+1][1] };
#pragma unroll
            for (int nf = 0; nf < 8; nf++) {
                uint32_t bf[2];
                LDSM_X2T(bf, vbuf + (ks*16 + b_roff + b_koff)*FH + nf*16);
                MMA16816(oacc[nf], ap, bf[0], bf[1]);
            }
        }
        __syncthreads();
        int nt = it + 2;
        if (nt < 16) {
            uint32_t kd = kb + (it & 1)*9216, vd = vb + (it & 1)*9216;
#pragma unroll
            for (int i = 0; i < 4; i++) {
                int e = tid + i*128, r = e >> 3, c = e & 7;
                cp16(kd + r*FH + c*16, Kp0 + (size_t)(nt*64 + r)*LDQ + c*8);
                cp16(vd + r*FH + c*16, Vp0 + (size_t)(nt*64 + r)*LDQ + c*8);
            }
        }
        CP_COMMIT();
    }

    l0r += __shfl_xor_sync(0xffffffffu, l0r, 1);
    l0r += __shfl_xor_sync(0xffffffffu, l0r, 2);
    l1r += __shfl_xor_sync(0xffffffffu, l1r, 1);
    l1r += __shfl_xor_sync(0xffffffffu, l1r, 2);
    float inv0 = l0r > 0.f ? 1.0f/l0r : 0.f;
    float inv1 = l1r > 0.f ? 1.0f/l1r : 0.f;

    __half* Cp = C + ((size_t)(b*L + l0 + r0loc))*D + hh*DQ;
#pragma unroll
    for (int nf = 0; nf < 8; nf++) {
        int c0 = nf*8 + bq*2;
        *(__half2*)(Cp + c0)        = __floats2half2_rn(oacc[nf][0]*inv0, oacc[nf][1]*inv0);
        *(__half2*)(Cp + 8*D + c0)  = __floats2half2_rn(oacc[nf][2]*inv1, oacc[nf][3]*inv1);
    }
}

// ================= residual + layernorm (all-fp16 streams, fp32 math) =======
__global__ void addln_kernel(const __half* __restrict__ t,
                             const float* __restrict__ gamma, const float* __restrict__ beta) {
    int row = blockIdx.x;
    int tid = threadIdx.x;
    __half2* hr = (__half2*)(g_h16 + (size_t)row*D);
    const __half2* tr = (const __half2*)(t + (size_t)row*D);
    float2 v[2]; float sum = 0.f, sq = 0.f;
#pragma unroll
    for (int i = 0; i < 2; i++) {
        int p = tid + i*256;                    // pair index 0..511
        float2 hv = __half22float2(hr[p]);
        float2 tv = __half22float2(tr[p]);
        float x0 = hv.x + tv.x, x1 = hv.y + tv.y;
        v[i].x = x0; v[i].y = x1;
        sum += x0 + x1; sq += x0*x0 + x1*x1;
    }
#pragma unroll
    for (int o = 16; o; o >>= 1) {
        sum += __shfl_xor_sync(0xffffffffu, sum, o);
        sq  += __shfl_xor_sync(0xffffffffu, sq,  o);
    }
    __shared__ float s1[8], s2[8];
    int warp = tid >> 5, lane = tid & 31;
    if (lane == 0) { s1[warp] = sum; s2[warp] = sq; }
    __syncthreads();
    float ts = 0.f, tq = 0.f;
#pragma unroll
    for (int i = 0; i < 8; i++) { ts += s1[i]; tq += s2[i]; }
    float mean = ts * (1.0f/D);
    float var  = tq * (1.0f/D) - mean*mean;
    float rstd = rsqrtf(var + 1e-5f);
#pragma unroll
    for (int i = 0; i < 2; i++) {
        int p = tid + i*256;
        float r0 = (v[i].x - mean)*rstd*gamma[p*2]   + beta[p*2];
        float r1 = (v[i].y - mean)*rstd*gamma[p*2+1] + beta[p*2+1];
        hr[p] = __floats2half2_rn(r0, r1);
    }
}

// ================= layer-6 small path (8 last-token rows) ===================
__global__ void wo_small(const __half* __restrict__ ctx, const __half* __restrict__ w,
                         const float* __restrict__ bias) {
    int b = blockIdx.y, n = blockIdx.x*256 + threadIdx.x;
    const __half2* a  = (const __half2*)(ctx + ((size_t)b*L + (L-1))*D);
    const __half2* wp = (const __half2*)(w + (size_t)n*D);
    float acc = 0.f;
#pragma unroll 8
    for (int k = 0; k < D/2; k++) {
        float2 av = __half22float2(a[k]), wv = __half22float2(wp[k]);
        acc += av.x*wv.x + av.y*wv.y;
    }
    g_trow[b*D + n] = acc + bias[n];
}

__global__ void ff1_small(const __half* __restrict__ w, const float* __restrict__ bias) {
    int b = blockIdx.y, n = blockIdx.x*256 + threadIdx.x;
    const __half2* a  = (const __half2*)(g_hrow16 + (size_t)b*D);
    const __half2* wp = (const __half2*)(w + (size_t)n*D);
    float acc = 0.f;
#pragma unroll 8
    for (int k = 0; k < D/2; k++) {
        float2 av = __half22float2(a[k]), wv = __half22float2(wp[k]);
        acc += av.x*wv.x + av.y*wv.y;
    }
    g_frow16[(size_t)b*DFF + n] = __float2half(fmaxf(acc + bias[n], 0.f));
}

__global__ void ff2_small(const __half* __restrict__ w, const float* __restrict__ bias) {
    int b = blockIdx.y, n = blockIdx.x*256 + threadIdx.x;
    const __half2* a  = (const __half2*)(g_frow16 + (size_t)b*DFF);
    const __half2* wp = (const __half2*)(w + (size_t)n*DFF);
    float acc = 0.f;
#pragma unroll 8
    for (int k = 0; k < DFF/2; k++) {
        float2 av = __half22float2(a[k]), wv = __half22float2(wp[k]);
        acc += av.x*wv.x + av.y*wv.y;
    }
    g_trow[b*D + n] = acc + bias[n];
}

// hsel 0: h from g_h16 last rows -> g_hrow/g_hrow16;  1: g_hrow -> g_hfin
__global__ void addln_small(const float* __restrict__ gamma, const float* __restrict__ beta,
                            int hsel) {
    int b = blockIdx.x, tid = threadIdx.x;
    const float* tr = g_trow + (size_t)b*D;
    float v[4]; float sum = 0.f, sq = 0.f;
#pragma unroll
    for (int i = 0; i < 4; i++) {
        int c = tid + i*256;
        float hv = hsel ? g_hrow[(size_t)b*D + c]
                        : __half2float(g_h16[((size_t)b*L + (L-1))*D + c]);
        float x = hv + tr[c];
        v[i] = x; sum += x; sq += x*x;
    }
#pragma unroll
    for (int o = 16; o; o >>= 1) {
        sum += __shfl_xor_sync(0xffffffffu, sum, o);
        sq  += __shfl_xor_sync(0xffffffffu, sq,  o);
    }
    __shared__ float s1[8], s2[8];
    int warp = tid >> 5, lane = tid & 31;
    if (lane == 0) { s1[warp] = sum; s2[warp] = sq; }
    __syncthreads();
    float ts = 0.f, tq = 0.f;
#pragma unroll
    for (int i = 0; i < 8; i++) { ts += s1[i]; tq += s2[i]; }
    float mean = ts * (1.0f/D);
    float var  = tq * (1.0f/D) - mean*mean;
    float rstd = rsqrtf(var + 1e-5f);
#pragma unroll
    for (int i = 0; i < 4; i++) {
        int c = tid + i*256;
        float r = (v[i] - mean)*rstd*gamma[c] + beta[c];
        if (hsel) g_hfin[b*D + c] = r;
        else { g_hrow[b*D + c] = r; g_hrow16[b*D + c] = __float2half(r); }
    }
}

// ================= final logits + log-softmax ===============================
__global__ void final_kernel(const float* __restrict__ ow, const float* __restrict__ ob,
                             float* __restrict__ out) {
    int b = blockIdx.x;
    const float* hr = g_hfin + (size_t)b*D;
    int a = threadIdx.x >> 5, lane = threadIdx.x & 31;
    float s = 0.f;
    for (int c = lane; c < D; c += 32) s += hr[c] * ow[c*16 + a];
#pragma unroll
    for (int o = 16; o; o >>= 1) s += __shfl_down_sync(0xffffffffu, s, o);
    __shared__ float lg[16];
    if (lane == 0) lg[a] = s + ob[a];
    __syncthreads();
    if (threadIdx.x == 0) {
        float mx = lg[0];
#pragma unroll
        for (int i = 1; i < 16; i++) mx = fmaxf(mx, lg[i]);
        float sum = 0.f;
#pragma unroll
        for (int i = 0; i < 16; i++) sum += expf(lg[i] - mx);
        float lse = mx + logf(sum);
#pragma unroll
        for (int i = 0; i < 16; i++) out[b*16 + i] = lg[i] - lse;
    }
}

// ================= launch ====================================================
extern "C" void kernel_launch(void* const* d_in, const int* in_sizes, int n_in,
                              void* d_out, int out_size) {
    const int*   x     = (const int*)  d_in[0];
    const int*   mask  = (const int*)  d_in[1];
    const float* embed = (const float*)d_in[2];
    const float* Wq    = (const float*)d_in[3];
    const float* Wk    = (const float*)d_in[4];
    const float* Wv    = (const float*)d_in[5];
    const float* Wo_w  = (const float*)d_in[6];
    const float* Wo_b  = (const float*)d_in[7];
    const float* ln1_s = (const float*)d_in[8];
    const float* ln1_b = (const float*)d_in[9];
    const float* ff_w1 = (const float*)d_in[10];
    const float* ff_b1 = (const float*)d_in[11];
    const float* ff_w2 = (const float*)d_in[12];
    const float* ff_b2 = (const float*)d_in[13];
    const float* ln2_s = (const float*)d_in[14];
    const float* ln2_b = (const float*)d_in[15];
    const float* out_w = (const float*)d_in[16];
    const float* out_b = (const float*)d_in[17];
    float* out = (float*)d_out;

    __half *pt16, *ph16, *pqkv16, *pctx16, *pff16, *pwqkv, *pwo, *pw1, *pw2;
    cudaGetSymbolAddress((void**)&pt16, g_t16);
    cudaGetSymbolAddress((void**)&ph16,   g_h16);
    cudaGetSymbolAddress((void**)&pqkv16, g_qkv16);
    cudaGetSymbolAddress((void**)&pctx16, g_ctx16);
    cudaGetSymbolAddress((void**)&pff16,  g_ff16);
    cudaGetSymbolAddress((void**)&pwqkv, g_wqkv16);
    cudaGetSymbolAddress((void**)&pwo,  g_wo16);
    cudaGetSymbolAddress((void**)&pw1,  g_w116);
    cudaGetSymbolAddress((void**)&pw2,  g_w216);

    cudaFuncSetAttribute(gemm_mma<false,false>, cudaFuncAttributeMaxDynamicSharedMemorySize, GEMM_SMEM);
    cudaFuncSetAttribute(gemm_mma<true,false>,  cudaFuncAttributeMaxDynamicSharedMemorySize, GEMM_SMEM);
    cudaFuncSetAttribute(gemm_mma<true,true>,   cudaFuncAttributeMaxDynamicSharedMemorySize, GEMM_SMEM);

    invdiv_kernel<<<1, 512>>>();
    pe_kernel<<<(L*(D/2))/256, 256>>>();
    mbits_kernel<<<(BATCH*L*(L/32))/256, 256>>>(mask);
    embed_kernel<<<MROWS, 256>>>(x, embed);

    dim3 tb(32, 8);
    wtr_qkv<<<dim3(2, 32, NLAYERS*H), tb>>>(Wq, pwqkv, 0);
    wtr_qkv<<<dim3(2, 32, NLAYERS*H), tb>>>(Wk, pwqkv, 1);
    wtr_qkv<<<dim3(2, 32, NLAYERS*H), tb>>>(Wv, pwqkv, 2);
    wtr_kernel<<<dim3(32, 32, NLAYERS), tb>>>(Wo_w, pwo, 1024, 1024);
    wtr_kernel<<<dim3(128, 32, NLAYERS), tb>>>(ff_w1, pw1, 1024, 4096);
    wtr_kernel<<<dim3(32, 128, NLAYERS), tb>>>(ff_w2, pw2, 4096, 1024);

    dim3 gQKV(3072/GBN, MROWS/GBM);   // (24, 64)
    dim3 gD(D/GBN, MROWS/GBM);        // (8, 64)
    dim3 gF(DFF/GBN, MROWS/GBM);      // (32, 64)
    for (int i = 0; i < NLAYERS; i++) {
        int last = (i == NLAYERS-1);
        size_t wOff = (size_t)i*D*D, fOff = (size_t)i*DFF*D;
        gemm_mma<false,false><<<gQKV, 256, GEMM_SMEM>>>(
            ph16, pwqkv + (size_t)i*3072*1024, nullptr, pqkv16, D, 3072, last);

        if (!last) {
            flash_mma<<<dim3(16, BATCH*H), 128>>>(pqkv16, pctx16, 0);
            gemm_mma<true,false><<<gD, 256, GEMM_SMEM>>>(
                pctx16, pwo + wOff, Wo_b + (size_t)i*D, pt16, D, D, 0);
            addln_kernel<<<MROWS, 256>>>(pt16, ln1_s + (size_t)i*D, ln1_b + (size_t)i*D);
            gemm_mma<true,true><<<gF, 256, GEMM_SMEM>>>(
                ph16, pw1 + fOff, ff_b1 + (size_t)i*DFF, pff16, D, DFF, 0);
            gemm_mma<true,false><<<gD, 256, GEMM_SMEM>>>(
                pff16, pw2 + fOff, ff_b2 + (size_t)i*D, pt16, DFF, D, 0);
            addln_kernel<<<MROWS, 256>>>(pt16, ln2_s + (size_t)i*D, ln2_b + (size_t)i*D);
        } else {
            flash_mma<<<dim3(1, BATCH*H), 128>>>(pqkv16, pctx16, 960);
            wo_small<<<dim3(4, 8), 256>>>(pctx16, pwo + wOff, Wo_b + (size_t)i*D);
            addln_small<<<8, 256>>>(ln1_s + (size_t)i*D, ln1_b + (size_t)i*D, 0);
            ff1_small<<<dim3(16, 8), 256>>>(pw1 + fOff, ff_b1 + (size_t)i*DFF);
            ff2_small<<<dim3(4, 8), 256>>>(pw2 + fOff, ff_b2 + (size_t)i*D);
            addln_small<<<8, 256>>>(ln2_s + (size_t)i*D, ln2_b + (size_t)i*D, 1);
        }
    }
    final_kernel<<<BATCH, 512>>>(out_w, out_b, out);
}